// round 1
// baseline (speedup 1.0000x reference)
#include <cuda_runtime.h>
#include <cuda_bf16.h>
#include <math.h>

#define Bsz    2
#define Tseq   2048
#define Hdim   2560
#define NH     8
#define NKV    4
#define Dh     256
#define WINDOW 1024
#define QKVN   4096          // 2048 q | 1024 k | 1024 v
#define ROWS   (Bsz*Tseq)    // 4096
#define ATTN_N (NH*Dh)       // 2048

// ---------------- scratch (device globals: no allocations allowed) ----------
__device__ float g_qkv[(size_t)ROWS * QKVN];   // 64 MB
__device__ float g_att[(size_t)ROWS * ATTN_N]; // 32 MB
__device__ float g_sin[(size_t)ROWS * (Dh/2)];
__device__ float g_cos[(size_t)ROWS * (Dh/2)];
__device__ int   g_first[Bsz];
__device__ int   g_zero_int = 0;

// ---------------- pos helper: first index of max(segment row) ---------------
__global__ void seg_first_kernel(const int* __restrict__ seg) {
    __shared__ int smax;
    __shared__ int sidx;
    int b = blockIdx.x, tid = threadIdx.x;
    if (tid == 0) { smax = -2147483647; sidx = 2147483647; }
    __syncthreads();
    int mx = -2147483647;
    for (int t = tid; t < Tseq; t += blockDim.x) mx = max(mx, seg[b*Tseq + t]);
    atomicMax(&smax, mx);
    __syncthreads();
    int mv = smax;
    int mi = 2147483647;
    for (int t = tid; t < Tseq; t += blockDim.x)
        if (seg[b*Tseq + t] == mv) mi = min(mi, t);
    atomicMin(&sidx, mi);
    __syncthreads();
    if (tid == 0) g_first[b] = sidx;
}

// ---------------- rope sin/cos tables ----------------------------------------
__global__ void rope_table_kernel(const int* __restrict__ seg,
                                  const int* __restrict__ cur_ind) {
    int row = blockIdx.x;            // b*T + t
    int k   = threadIdx.x;           // 0..127
    int b = row / Tseq, t = row % Tseq;
    int sv = seg[row];
    long long pos = (sv != 0) ? (long long)(t - g_first[b]) : (1ll << 30);
    pos += (long long)cur_ind[0];
    float posf = (float)pos;
    float freq = powf(10000.0f, -((float)(2*k)) / (float)Dh);
    float ang  = posf * freq;
    g_sin[(size_t)row*128 + k] = sinf(ang);
    g_cos[(size_t)row*128 + k] = cosf(ang);
}

// ---------------- generic 64x64 fp32 tiled GEMM ------------------------------
// C[M,N] = A[M,K] * B[K,N]; grid = (N/64, M/64), 256 threads, 4x4 per thread.
__global__ void __launch_bounds__(256) gemm64_kernel(
    const float* __restrict__ A, int lda,
    const float* __restrict__ Bm, int ldb,
    float* __restrict__ C, int ldc, int K)
{
    __shared__ float As[16][68];
    __shared__ float Bs[16][68];
    int m0 = blockIdx.y * 64, n0 = blockIdx.x * 64;
    int tid = threadIdx.x;
    int tx = tid & 15, ty = tid >> 4;
    // A-load mapping: 4 consecutive lanes cover 16 consecutive k of one row
    int ak = (tid & 3) << 2, am = tid >> 2;
    // B-load mapping: 16 lanes cover 64 consecutive n of one k-row
    int bn = (tid & 15) << 2, bk = tid >> 4;
    float acc[4][4];
#pragma unroll
    for (int i = 0; i < 4; i++)
#pragma unroll
        for (int j = 0; j < 4; j++) acc[i][j] = 0.f;

    const float* Ap = A + (size_t)(m0 + am) * lda + ak;
    const float* Bp = Bm + (size_t)bk * ldb + n0 + bn;

    for (int k0 = 0; k0 < K; k0 += 16) {
        float4 av = *(const float4*)(Ap + k0);
        float4 bv = *(const float4*)(Bp + (size_t)k0 * ldb);
        __syncthreads();
        As[ak+0][am] = av.x; As[ak+1][am] = av.y;
        As[ak+2][am] = av.z; As[ak+3][am] = av.w;
        *(float4*)&Bs[bk][bn] = bv;
        __syncthreads();
#pragma unroll
        for (int kk = 0; kk < 16; kk++) {
            float4 a = *(const float4*)&As[kk][ty << 2];
            float4 b = *(const float4*)&Bs[kk][tx << 2];
            acc[0][0] += a.x*b.x; acc[0][1] += a.x*b.y; acc[0][2] += a.x*b.z; acc[0][3] += a.x*b.w;
            acc[1][0] += a.y*b.x; acc[1][1] += a.y*b.y; acc[1][2] += a.y*b.z; acc[1][3] += a.y*b.w;
            acc[2][0] += a.z*b.x; acc[2][1] += a.z*b.y; acc[2][2] += a.z*b.z; acc[2][3] += a.z*b.w;
            acc[3][0] += a.w*b.x; acc[3][1] += a.w*b.y; acc[3][2] += a.w*b.z; acc[3][3] += a.w*b.w;
        }
    }
#pragma unroll
    for (int i = 0; i < 4; i++) {
        float4 o = make_float4(acc[i][0], acc[i][1], acc[i][2], acc[i][3]);
        *(float4*)(C + (size_t)(m0 + (ty<<2) + i) * ldc + n0 + (tx<<2)) = o;
    }
}

// ---------------- RMSNorm + RoPE in place on q/k columns ---------------------
__global__ void __launch_bounds__(256) rmsnorm_rope_kernel(
    const float* __restrict__ qsc, const float* __restrict__ ksc)
{
    int bid = blockIdx.x;
    int row = bid / (NH + NKV);
    int hi  = bid % (NH + NKV);
    int off; const float* sc;
    if (hi < NH) { off = hi * Dh;               sc = qsc; }
    else         { off = NH*Dh + (hi-NH) * Dh;  sc = ksc; }
    float* p = g_qkv + (size_t)row * QKVN + off;
    int tid = threadIdx.x;
    float x = p[tid];
    float ss = x * x;
#pragma unroll
    for (int o = 16; o; o >>= 1) ss += __shfl_xor_sync(0xffffffffu, ss, o);
    __shared__ float red[8];
    __shared__ float tot;
    __shared__ float sy[256];
    if ((tid & 31) == 0) red[tid >> 5] = ss;
    __syncthreads();
    if (tid == 0) {
        float t = 0.f;
        for (int i = 0; i < 8; i++) t += red[i];
        tot = t;
    }
    __syncthreads();
    float rms = rsqrtf(tot * (1.0f / Dh) + 1e-6f);
    float y = x * rms * (1.0f + sc[tid]);
    sy[tid] = y;
    __syncthreads();
    int kidx = tid & 127;
    float s_ = g_sin[(size_t)row*128 + kidx];
    float c_ = g_cos[(size_t)row*128 + kidx];
    float out;
    if (tid < 128) out = y * c_ - sy[tid + 128] * s_;
    else           out = y * c_ + sy[tid - 128] * s_;
    p[tid] = out;
}

// ---------------- flash attention (fp32, sliding window, GQA) ----------------
#define BQ    64
#define BKT   64
#define PADQ  65
#define PADP  68
#define SM_SCALE 0.0625f   // 256^-0.5

__global__ void __launch_bounds__(256) attn_kernel() {
    extern __shared__ float smd[];
    float* Qs = smd;                          // [256][PADQ] d-major
    float* Ks = Qs + 256 * PADQ;              // [256][PADQ] d-major
    float* Vs = Ks + 256 * PADQ;              // [64][256]
    float* Ps = Vs + 64 * 256;                // [64][PADP]
    int q0 = blockIdx.x * BQ;
    int h  = blockIdx.y, b = blockIdx.z;
    int tid = threadIdx.x;
    int tx = tid & 15, ty = tid >> 4;
    int kvh = h >> 1;
    const float* baseq = g_qkv + (size_t)b * Tseq * QKVN + h * Dh;
    const float* basek = g_qkv + (size_t)b * Tseq * QKVN + NH*Dh + kvh * Dh;
    const float* basev = g_qkv + (size_t)b * Tseq * QKVN + NH*Dh + NKV*Dh + kvh * Dh;

    // load Q transposed (d-major)
    {
        int dg = tid & 15, r = tid >> 4;
#pragma unroll
        for (int it = 0; it < 4; it++) {
            int d0 = (it*16 + dg) * 4;
#pragma unroll
            for (int kit = 0; kit < 4; kit++) {
                int qr = r + kit*16;
                float4 v = *(const float4*)(baseq + (size_t)(q0+qr)*QKVN + d0);
                Qs[(d0+0)*PADQ + qr] = v.x;
                Qs[(d0+1)*PADQ + qr] = v.y;
                Qs[(d0+2)*PADQ + qr] = v.z;
                Qs[(d0+3)*PADQ + qr] = v.w;
            }
        }
    }

    float m_i[4], l_i[4], O[4][16];
#pragma unroll
    for (int i = 0; i < 4; i++) {
        m_i[i] = -1e30f; l_i[i] = 0.f;
#pragma unroll
        for (int j = 0; j < 16; j++) O[i][j] = 0.f;
    }

    int kstart = q0 - (WINDOW - 1); if (kstart < 0) kstart = 0;
    int kt0 = kstart & ~(BKT - 1);

    for (int kt = kt0; kt < q0 + BQ; kt += BKT) {
        __syncthreads();   // protect Ks/Vs from previous iteration's readers
        {
            int dg = tid & 15, r = tid >> 4;
#pragma unroll
            for (int it = 0; it < 4; it++) {
                int d0 = (it*16 + dg) * 4;
#pragma unroll
                for (int kit = 0; kit < 4; kit++) {
                    int kr = r + kit*16;
                    float4 v = *(const float4*)(basek + (size_t)(kt+kr)*QKVN + d0);
                    Ks[(d0+0)*PADQ + kr] = v.x;
                    Ks[(d0+1)*PADQ + kr] = v.y;
                    Ks[(d0+2)*PADQ + kr] = v.z;
                    Ks[(d0+3)*PADQ + kr] = v.w;
                }
            }
#pragma unroll
            for (int c = 0; c < 16; c++) {
                int fidx = tid + c*256;
                int kr = fidx >> 6, d4 = (fidx & 63) << 2;
                *(float4*)&Vs[kr*256 + d4] =
                    *(const float4*)(basev + (size_t)(kt+kr)*QKVN + d4);
            }
        }
        __syncthreads();

        // S = Q K^T (4x4 per thread)
        float s[4][4];
#pragma unroll
        for (int i = 0; i < 4; i++)
#pragma unroll
            for (int j = 0; j < 4; j++) s[i][j] = 0.f;
        const float* qp = Qs + (ty << 2);
        const float* kp = Ks + (tx << 2);
#pragma unroll 4
        for (int d = 0; d < 256; d++) {
            float a0 = qp[d*PADQ+0], a1 = qp[d*PADQ+1], a2 = qp[d*PADQ+2], a3 = qp[d*PADQ+3];
            float b0 = kp[d*PADQ+0], b1 = kp[d*PADQ+1], b2 = kp[d*PADQ+2], b3 = kp[d*PADQ+3];
            s[0][0] += a0*b0; s[0][1] += a0*b1; s[0][2] += a0*b2; s[0][3] += a0*b3;
            s[1][0] += a1*b0; s[1][1] += a1*b1; s[1][2] += a1*b2; s[1][3] += a1*b3;
            s[2][0] += a2*b0; s[2][1] += a2*b1; s[2][2] += a2*b2; s[2][3] += a2*b3;
            s[3][0] += a3*b0; s[3][1] += a3*b1; s[3][2] += a3*b2; s[3][3] += a3*b3;
        }

        // online softmax (rows shared across 16-lane groups)
#pragma unroll
        for (int i = 0; i < 4; i++) {
            int qg = q0 + (ty<<2) + i;
            float mx = -1e30f;
#pragma unroll
            for (int j = 0; j < 4; j++) {
                int kg = kt + (tx<<2) + j;
                float sv = s[i][j] * SM_SCALE;
                bool valid = (kg <= qg) && (qg - kg < WINDOW);
                sv = valid ? sv : -1e30f;
                s[i][j] = sv;
                mx = fmaxf(mx, sv);
            }
#pragma unroll
            for (int o = 8; o; o >>= 1) mx = fmaxf(mx, __shfl_xor_sync(0xffffffffu, mx, o));
            float mnew  = fmaxf(m_i[i], mx);
            float alpha = __expf(m_i[i] - mnew);
            float rs = 0.f;
#pragma unroll
            for (int j = 0; j < 4; j++) {
                float pv = (s[i][j] > -1e29f) ? __expf(s[i][j] - mnew) : 0.f;
                s[i][j] = pv; rs += pv;
            }
#pragma unroll
            for (int o = 8; o; o >>= 1) rs += __shfl_xor_sync(0xffffffffu, rs, o);
            l_i[i] = l_i[i] * alpha + rs;
            m_i[i] = mnew;
#pragma unroll
            for (int j = 0; j < 16; j++) O[i][j] *= alpha;
            *(float4*)&Ps[((ty<<2)+i)*PADP + (tx<<2)] =
                make_float4(s[i][0], s[i][1], s[i][2], s[i][3]);
        }
        __syncthreads();

        // O += P V  (4 q-rows x 16 d-cols per thread)
#pragma unroll 2
        for (int k = 0; k < BKT; k++) {
            const float* vr = Vs + k*256 + (tx<<4);
            float4 v0 = *(const float4*)(vr + 0);
            float4 v1 = *(const float4*)(vr + 4);
            float4 v2 = *(const float4*)(vr + 8);
            float4 v3 = *(const float4*)(vr + 12);
#pragma unroll
            for (int i = 0; i < 4; i++) {
                float pv = Ps[((ty<<2)+i)*PADP + k];
                O[i][0]  += pv*v0.x; O[i][1]  += pv*v0.y; O[i][2]  += pv*v0.z; O[i][3]  += pv*v0.w;
                O[i][4]  += pv*v1.x; O[i][5]  += pv*v1.y; O[i][6]  += pv*v1.z; O[i][7]  += pv*v1.w;
                O[i][8]  += pv*v2.x; O[i][9]  += pv*v2.y; O[i][10] += pv*v2.z; O[i][11] += pv*v2.w;
                O[i][12] += pv*v3.x; O[i][13] += pv*v3.y; O[i][14] += pv*v3.z; O[i][15] += pv*v3.w;
            }
        }
    }

    // epilogue
#pragma unroll
    for (int i = 0; i < 4; i++) {
        float inv = 1.f / l_i[i];
        int q = q0 + (ty<<2) + i;
        float* op = g_att + (size_t)(b*Tseq + q) * ATTN_N + h * Dh + (tx<<4);
        *(float4*)(op + 0)  = make_float4(O[i][0]*inv,  O[i][1]*inv,  O[i][2]*inv,  O[i][3]*inv);
        *(float4*)(op + 4)  = make_float4(O[i][4]*inv,  O[i][5]*inv,  O[i][6]*inv,  O[i][7]*inv);
        *(float4*)(op + 8)  = make_float4(O[i][8]*inv,  O[i][9]*inv,  O[i][10]*inv, O[i][11]*inv);
        *(float4*)(op + 12) = make_float4(O[i][12]*inv, O[i][13]*inv, O[i][14]*inv, O[i][15]*inv);
    }
}

// ---------------- launch ------------------------------------------------------
extern "C" void kernel_launch(void* const* d_in, const int* in_sizes, int n_in,
                              void* d_out, int out_size) {
    const float* x   = (const float*)d_in[0];
    const float* Wq  = (const float*)d_in[1];
    const float* Wk  = (const float*)d_in[2];
    const float* Wv  = (const float*)d_in[3];
    const float* Wo  = (const float*)d_in[4];
    const float* qsc = (const float*)d_in[5];
    const float* ksc = (const float*)d_in[6];
    const int*   seg = (const int*)d_in[7];
    float* out = (float*)d_out;

    const int* cur;
    if (n_in > 9) cur = (const int*)d_in[9];
    else {
        void* zp; cudaGetSymbolAddress(&zp, g_zero_int);
        cur = (const int*)zp;
    }

    float *qkv, *att;
    cudaGetSymbolAddress((void**)&qkv, g_qkv);
    cudaGetSymbolAddress((void**)&att, g_att);

    seg_first_kernel<<<Bsz, 256>>>(seg);
    rope_table_kernel<<<ROWS, 128>>>(seg, cur);

    // fused QKV projections (three column slabs of one [4096,4096] scratch)
    gemm64_kernel<<<dim3(2048/64, ROWS/64), 256>>>(x, Hdim, Wq, 2048, qkv,        QKVN, Hdim);
    gemm64_kernel<<<dim3(1024/64, ROWS/64), 256>>>(x, Hdim, Wk, 1024, qkv + 2048, QKVN, Hdim);
    gemm64_kernel<<<dim3(1024/64, ROWS/64), 256>>>(x, Hdim, Wv, 1024, qkv + 3072, QKVN, Hdim);

    rmsnorm_rope_kernel<<<ROWS * (NH + NKV), 256>>>(qsc, ksc);

    size_t smem = (size_t)(2*256*PADQ + 64*256 + 64*PADP) * sizeof(float); // 216064 B
    cudaFuncSetAttribute(attn_kernel, cudaFuncAttributeMaxDynamicSharedMemorySize, (int)smem);
    attn_kernel<<<dim3(Tseq/BQ, NH, Bsz), 256, smem>>>();

    // output projection -> d_out
    gemm64_kernel<<<dim3(Hdim/64, ROWS/64), 256>>>(att, ATTN_N, Wo, Hdim, out, Hdim, ATTN_N);
}

// round 3
// speedup vs baseline: 1.0974x; 1.0974x over previous
#include <cuda_runtime.h>
#include <cuda_bf16.h>
#include <math.h>
#include <stdint.h>

#define Bsz    2
#define Tseq   2048
#define Hdim   2560
#define NH     8
#define NKV    4
#define Dh     256
#define WINDOW 1024
#define QKVN   4096          // 2048 q | 1024 k | 1024 v
#define ROWS   (Bsz*Tseq)    // 4096
#define ATTN_N (NH*Dh)       // 2048

// ---------------- scratch (device globals: no allocations allowed) ----------
__device__ float g_qkv[(size_t)ROWS * QKVN];   // 64 MB
__device__ float g_att[(size_t)ROWS * ATTN_N]; // 32 MB
__device__ float g_sin[(size_t)ROWS * (Dh/2)];
__device__ float g_cos[(size_t)ROWS * (Dh/2)];
__device__ int   g_first[Bsz];
__device__ int   g_zero_int = 0;

// transposed + tf32-split weights (hi/lo planes), K-major [N, K]
__device__ float g_wqT_hi[(size_t)2048 * 2560];
__device__ float g_wqT_lo[(size_t)2048 * 2560];
__device__ float g_wkT_hi[(size_t)1024 * 2560];
__device__ float g_wkT_lo[(size_t)1024 * 2560];
__device__ float g_wvT_hi[(size_t)1024 * 2560];
__device__ float g_wvT_lo[(size_t)1024 * 2560];
__device__ float g_woT_hi[(size_t)2560 * 2048];
__device__ float g_woT_lo[(size_t)2560 * 2048];

// ---------------- helpers ------------------------------------------------------
__device__ __forceinline__ uint32_t smem_u32(const void* p) {
    uint32_t a;
    asm("{ .reg .u64 t; cvta.to.shared.u64 t, %1; cvt.u32.u64 %0, t; }"
        : "=r"(a) : "l"(p));
    return a;
}
__device__ __forceinline__ float cvt_tf32(float x) {
    float r; asm("cvt.rna.tf32.f32 %0, %1;" : "=f"(r) : "f"(x)); return r;
}
__device__ __forceinline__ void mma_tf32(float* c,
    uint32_t a0, uint32_t a1, uint32_t a2, uint32_t a3,
    uint32_t b0, uint32_t b1)
{
    asm volatile(
        "mma.sync.aligned.m16n8k8.row.col.f32.tf32.tf32.f32 "
        "{%0,%1,%2,%3}, {%4,%5,%6,%7}, {%8,%9}, {%0,%1,%2,%3};"
        : "+f"(c[0]), "+f"(c[1]), "+f"(c[2]), "+f"(c[3])
        : "r"(a0), "r"(a1), "r"(a2), "r"(a3), "r"(b0), "r"(b1));
}
#define CP_ASYNC16(dst, src) \
    asm volatile("cp.async.cg.shared.global [%0], [%1], 16;" :: "r"(dst), "l"(src))
#define CP_COMMIT() asm volatile("cp.async.commit_group;" ::: "memory")
#define CP_WAIT0()  asm volatile("cp.async.wait_group 0;" ::: "memory")

// ---------------- pos helper ----------------------------------------------------
__global__ void seg_first_kernel(const int* __restrict__ seg) {
    __shared__ int smax;
    __shared__ int sidx;
    int b = blockIdx.x, tid = threadIdx.x;
    if (tid == 0) { smax = -2147483647; sidx = 2147483647; }
    __syncthreads();
    int mx = -2147483647;
    for (int t = tid; t < Tseq; t += blockDim.x) mx = max(mx, seg[b*Tseq + t]);
    atomicMax(&smax, mx);
    __syncthreads();
    int mv = smax;
    int mi = 2147483647;
    for (int t = tid; t < Tseq; t += blockDim.x)
        if (seg[b*Tseq + t] == mv) mi = min(mi, t);
    atomicMin(&sidx, mi);
    __syncthreads();
    if (tid == 0) g_first[b] = sidx;
}

// ---------------- rope sin/cos tables --------------------------------------------
__global__ void rope_table_kernel(const int* __restrict__ seg,
                                  const int* __restrict__ cur_ind) {
    int row = blockIdx.x;
    int k   = threadIdx.x;
    int b = row / Tseq, t = row % Tseq;
    int sv = seg[row];
    long long pos = (sv != 0) ? (long long)(t - g_first[b]) : (1ll << 30);
    pos += (long long)cur_ind[0];
    float posf = (float)pos;
    float freq = powf(10000.0f, -((float)(2*k)) / (float)Dh);
    float ang  = posf * freq;
    g_sin[(size_t)row*128 + k] = sinf(ang);
    g_cos[(size_t)row*128 + k] = cosf(ang);
}

// ---------------- weight transpose + tf32 split ----------------------------------
__global__ void __launch_bounds__(256) transpose_split_kernel(
    const float* __restrict__ W, int K, int N,
    float* __restrict__ Thi, float* __restrict__ Tlo)
{
    __shared__ float tile[32][33];
    int k0 = blockIdx.x * 32, n0 = blockIdx.y * 32;
    int tx = threadIdx.x, ty = threadIdx.y;
#pragma unroll
    for (int i = 0; i < 32; i += 8)
        tile[ty + i][tx] = W[(size_t)(k0 + ty + i) * N + n0 + tx];
    __syncthreads();
#pragma unroll
    for (int i = 0; i < 32; i += 8) {
        float v = tile[tx][ty + i];
        float h = cvt_tf32(v);
        size_t o = (size_t)(n0 + ty + i) * K + k0 + tx;
        Thi[o] = h;
        Tlo[o] = cvt_tf32(v - h);
    }
}

// ---------------- mma.sync split-tf32 GEMM ---------------------------------------
// C[M,N] = A[M,K] * B^T ; B given K-major [N,K] hi/lo planes (already tf32-valued).
// CTA tile 128x128, 8 warps (2M x 4N), warp tile 64x32. K chunk = 32.
#define ASTRIDE 36
#define PLANE   (128*ASTRIDE)                 // floats per plane
#define STG_F   (4*PLANE)                     // floats per stage (Ahi,Alo,Bhi,Blo)
#define GEMM_SMEM (2*STG_F*4)                 // bytes = 147456

__global__ void __launch_bounds__(256, 1) gemm_mma_kernel(
    const float* __restrict__ A, int lda,
    const float* __restrict__ Bhi, const float* __restrict__ Blo,
    float* __restrict__ C, int ldc, int K)
{
    extern __shared__ float smf[];
    int tid  = threadIdx.x;
    int lane = tid & 31, wid = tid >> 5;
    int wm = wid >> 2, wn = wid & 3;
    int m0 = blockIdx.y * 128, n0 = blockIdx.x * 128;

    // loader mapping: 2 threads per row, each 16 consecutive floats (4x float4)
    int lrow = tid >> 1, lhalf = (tid & 1) * 16;
    const float* aP  = A   + (size_t)(m0 + lrow) * lda + lhalf;
    const float* bhP = Bhi + (size_t)(n0 + lrow) * K   + lhalf;
    const float* blP = Blo + (size_t)(n0 + lrow) * K   + lhalf;
    float* sRowA = smf + lrow * ASTRIDE + lhalf;          // + stage*STG_F (+PLANE for lo)
    uint32_t sRowB_hi = smem_u32(smf + 2*PLANE + lrow * ASTRIDE + lhalf);
    uint32_t sRowB_lo = smem_u32(smf + 3*PLANE + lrow * ASTRIDE + lhalf);

    float acc[4][4][4];
#pragma unroll
    for (int i = 0; i < 4; i++)
#pragma unroll
        for (int j = 0; j < 4; j++)
#pragma unroll
            for (int r = 0; r < 4; r++) acc[i][j][r] = 0.f;

    const int nc = K >> 5;
    float4 areg[4];

    // ---- prologue: chunk 0 ----
#pragma unroll
    for (int j = 0; j < 4; j++) areg[j] = *(const float4*)(aP + j*4);
#pragma unroll
    for (int j = 0; j < 4; j++) {
        CP_ASYNC16(sRowB_hi + j*16, bhP + j*4);
        CP_ASYNC16(sRowB_lo + j*16, blP + j*4);
    }
    CP_COMMIT();
#pragma unroll
    for (int j = 0; j < 4; j++) {
        float4 v = areg[j];
        float4 h, l;
        h.x = cvt_tf32(v.x); l.x = cvt_tf32(v.x - h.x);
        h.y = cvt_tf32(v.y); l.y = cvt_tf32(v.y - h.y);
        h.z = cvt_tf32(v.z); l.z = cvt_tf32(v.z - h.z);
        h.w = cvt_tf32(v.w); l.w = cvt_tf32(v.w - h.w);
        *(float4*)(sRowA + j*4)         = h;
        *(float4*)(sRowA + PLANE + j*4) = l;
    }
    CP_WAIT0();
    __syncthreads();

    for (int c = 0; c < nc; c++) {
        int s  = c & 1;
        int sn = s ^ 1;
        bool more = (c + 1) < nc;
        if (more) {
            int k0 = (c + 1) * 32;
#pragma unroll
            for (int j = 0; j < 4; j++) areg[j] = *(const float4*)(aP + k0 + j*4);
            uint32_t bh = sRowB_hi + sn * (STG_F * 4);
            uint32_t bl = sRowB_lo + sn * (STG_F * 4);
#pragma unroll
            for (int j = 0; j < 4; j++) {
                CP_ASYNC16(bh + j*16, bhP + k0 + j*4);
                CP_ASYNC16(bl + j*16, blP + k0 + j*4);
            }
            CP_COMMIT();
        }

        // ---- compute chunk c from stage s ----
        const float* As = smf + s * STG_F;
        const float* Bs = As + 2*PLANE;
        int arow = wm*64 + (lane >> 2);
        int brow = wn*32 + (lane >> 2);
#pragma unroll
        for (int k8 = 0; k8 < 4; k8++) {
            int kc = k8*8 + (lane & 3);
            uint32_t ah[4][4], al[4][4], bh[4][2], bl[4][2];
#pragma unroll
            for (int mt = 0; mt < 4; mt++) {
                const float* ab = As + (arow + mt*16) * ASTRIDE + kc;
                ah[mt][0] = __float_as_uint(ab[0]);
                ah[mt][1] = __float_as_uint(ab[8*ASTRIDE]);
                ah[mt][2] = __float_as_uint(ab[4]);
                ah[mt][3] = __float_as_uint(ab[8*ASTRIDE + 4]);
                al[mt][0] = __float_as_uint(ab[PLANE]);
                al[mt][1] = __float_as_uint(ab[PLANE + 8*ASTRIDE]);
                al[mt][2] = __float_as_uint(ab[PLANE + 4]);
                al[mt][3] = __float_as_uint(ab[PLANE + 8*ASTRIDE + 4]);
            }
#pragma unroll
            for (int nt = 0; nt < 4; nt++) {
                const float* bb = Bs + (brow + nt*8) * ASTRIDE + kc;
                bh[nt][0] = __float_as_uint(bb[0]);
                bh[nt][1] = __float_as_uint(bb[4]);
                bl[nt][0] = __float_as_uint(bb[PLANE]);
                bl[nt][1] = __float_as_uint(bb[PLANE + 4]);
            }
#pragma unroll
            for (int mt = 0; mt < 4; mt++)
#pragma unroll
                for (int nt = 0; nt < 4; nt++) {
                    float* cc = acc[mt][nt];
                    mma_tf32(cc, ah[mt][0], ah[mt][1], ah[mt][2], ah[mt][3],
                             bh[nt][0], bh[nt][1]);
                    mma_tf32(cc, al[mt][0], al[mt][1], al[mt][2], al[mt][3],
                             bh[nt][0], bh[nt][1]);
                    mma_tf32(cc, ah[mt][0], ah[mt][1], ah[mt][2], ah[mt][3],
                             bl[nt][0], bl[nt][1]);
                }
        }

        if (more) {
            float* sa = smf + sn * STG_F + lrow * ASTRIDE + lhalf;
#pragma unroll
            for (int j = 0; j < 4; j++) {
                float4 v = areg[j];
                float4 h, l;
                h.x = cvt_tf32(v.x); l.x = cvt_tf32(v.x - h.x);
                h.y = cvt_tf32(v.y); l.y = cvt_tf32(v.y - h.y);
                h.z = cvt_tf32(v.z); l.z = cvt_tf32(v.z - h.z);
                h.w = cvt_tf32(v.w); l.w = cvt_tf32(v.w - h.w);
                *(float4*)(sa + j*4)         = h;
                *(float4*)(sa + PLANE + j*4) = l;
            }
            CP_WAIT0();
        }
        __syncthreads();
    }

    // ---- epilogue ----
#pragma unroll
    for (int mt = 0; mt < 4; mt++) {
        int row0 = m0 + wm*64 + mt*16 + (lane >> 2);
#pragma unroll
        for (int nt = 0; nt < 4; nt++) {
            int col = n0 + wn*32 + nt*8 + 2*(lane & 3);
            float* cc = acc[mt][nt];
            *(float2*)(C + (size_t)row0 * ldc + col)       = make_float2(cc[0], cc[1]);
            *(float2*)(C + (size_t)(row0 + 8) * ldc + col) = make_float2(cc[2], cc[3]);
        }
    }
}

// ---------------- RMSNorm + RoPE in place on q/k columns --------------------------
__global__ void __launch_bounds__(256) rmsnorm_rope_kernel(
    const float* __restrict__ qsc, const float* __restrict__ ksc)
{
    int bid = blockIdx.x;
    int row = bid / (NH + NKV);
    int hi  = bid % (NH + NKV);
    int off; const float* sc;
    if (hi < NH) { off = hi * Dh;               sc = qsc; }
    else         { off = NH*Dh + (hi-NH) * Dh;  sc = ksc; }
    float* p = g_qkv + (size_t)row * QKVN + off;
    int tid = threadIdx.x;
    float x = p[tid];
    float ss = x * x;
#pragma unroll
    for (int o = 16; o; o >>= 1) ss += __shfl_xor_sync(0xffffffffu, ss, o);
    __shared__ float red[8];
    __shared__ float tot;
    __shared__ float sy[256];
    if ((tid & 31) == 0) red[tid >> 5] = ss;
    __syncthreads();
    if (tid == 0) {
        float t = 0.f;
        for (int i = 0; i < 8; i++) t += red[i];
        tot = t;
    }
    __syncthreads();
    float rms = rsqrtf(tot * (1.0f / Dh) + 1e-6f);
    float y = x * rms * (1.0f + sc[tid]);
    sy[tid] = y;
    __syncthreads();
    int kidx = tid & 127;
    float s_ = g_sin[(size_t)row*128 + kidx];
    float c_ = g_cos[(size_t)row*128 + kidx];
    float out;
    if (tid < 128) out = y * c_ - sy[tid + 128] * s_;
    else           out = y * c_ + sy[tid - 128] * s_;
    p[tid] = out;
}

// ---------------- flash attention (fp32, sliding window, GQA) ---------------------
#define BQ    64
#define BKT   64
#define PADQ  65
#define PADP  68
#define SM_SCALE 0.0625f

__global__ void __launch_bounds__(256) attn_kernel() {
    extern __shared__ float smd[];
    float* Qs = smd;
    float* Ks = Qs + 256 * PADQ;
    float* Vs = Ks + 256 * PADQ;
    float* Ps = Vs + 64 * 256;
    int q0 = blockIdx.x * BQ;
    int h  = blockIdx.y, b = blockIdx.z;
    int tid = threadIdx.x;
    int tx = tid & 15, ty = tid >> 4;
    int kvh = h >> 1;
    const float* baseq = g_qkv + (size_t)b * Tseq * QKVN + h * Dh;
    const float* basek = g_qkv + (size_t)b * Tseq * QKVN + NH*Dh + kvh * Dh;
    const float* basev = g_qkv + (size_t)b * Tseq * QKVN + NH*Dh + NKV*Dh + kvh * Dh;

    {
        int dg = tid & 15, r = tid >> 4;
#pragma unroll
        for (int it = 0; it < 4; it++) {
            int d0 = (it*16 + dg) * 4;
#pragma unroll
            for (int kit = 0; kit < 4; kit++) {
                int qr = r + kit*16;
                float4 v = *(const float4*)(baseq + (size_t)(q0+qr)*QKVN + d0);
                Qs[(d0+0)*PADQ + qr] = v.x;
                Qs[(d0+1)*PADQ + qr] = v.y;
                Qs[(d0+2)*PADQ + qr] = v.z;
                Qs[(d0+3)*PADQ + qr] = v.w;
            }
        }
    }

    float m_i[4], l_i[4], O[4][16];
#pragma unroll
    for (int i = 0; i < 4; i++) {
        m_i[i] = -1e30f; l_i[i] = 0.f;
#pragma unroll
        for (int j = 0; j < 16; j++) O[i][j] = 0.f;
    }

    int kstart = q0 - (WINDOW - 1); if (kstart < 0) kstart = 0;
    int kt0 = kstart & ~(BKT - 1);

    for (int kt = kt0; kt < q0 + BQ; kt += BKT) {
        __syncthreads();
        {
            int dg = tid & 15, r = tid >> 4;
#pragma unroll
            for (int it = 0; it < 4; it++) {
                int d0 = (it*16 + dg) * 4;
#pragma unroll
                for (int kit = 0; kit < 4; kit++) {
                    int kr = r + kit*16;
                    float4 v = *(const float4*)(basek + (size_t)(kt+kr)*QKVN + d0);
                    Ks[(d0+0)*PADQ + kr] = v.x;
                    Ks[(d0+1)*PADQ + kr] = v.y;
                    Ks[(d0+2)*PADQ + kr] = v.z;
                    Ks[(d0+3)*PADQ + kr] = v.w;
                }
            }
#pragma unroll
            for (int c = 0; c < 16; c++) {
                int fidx = tid + c*256;
                int kr = fidx >> 6, d4 = (fidx & 63) << 2;
                *(float4*)&Vs[kr*256 + d4] =
                    *(const float4*)(basev + (size_t)(kt+kr)*QKVN + d4);
            }
        }
        __syncthreads();

        float s[4][4];
#pragma unroll
        for (int i = 0; i < 4; i++)
#pragma unroll
            for (int j = 0; j < 4; j++) s[i][j] = 0.f;
        const float* qp = Qs + (ty << 2);
        const float* kp = Ks + (tx << 2);
#pragma unroll 4
        for (int d = 0; d < 256; d++) {
            float a0 = qp[d*PADQ+0], a1 = qp[d*PADQ+1], a2 = qp[d*PADQ+2], a3 = qp[d*PADQ+3];
            float b0 = kp[d*PADQ+0], b1 = kp[d*PADQ+1], b2 = kp[d*PADQ+2], b3 = kp[d*PADQ+3];
            s[0][0] += a0*b0; s[0][1] += a0*b1; s[0][2] += a0*b2; s[0][3] += a0*b3;
            s[1][0] += a1*b0; s[1][1] += a1*b1; s[1][2] += a1*b2; s[1][3] += a1*b3;
            s[2][0] += a2*b0; s[2][1] += a2*b1; s[2][2] += a2*b2; s[2][3] += a2*b3;
            s[3][0] += a3*b0; s[3][1] += a3*b1; s[3][2] += a3*b2; s[3][3] += a3*b3;
        }

#pragma unroll
        for (int i = 0; i < 4; i++) {
            int qg = q0 + (ty<<2) + i;
            float mx = -1e30f;
#pragma unroll
            for (int j = 0; j < 4; j++) {
                int kg = kt + (tx<<2) + j;
                float sv = s[i][j] * SM_SCALE;
                bool valid = (kg <= qg) && (qg - kg < WINDOW);
                sv = valid ? sv : -1e30f;
                s[i][j] = sv;
                mx = fmaxf(mx, sv);
            }
#pragma unroll
            for (int o = 8; o; o >>= 1) mx = fmaxf(mx, __shfl_xor_sync(0xffffffffu, mx, o));
            float mnew  = fmaxf(m_i[i], mx);
            float alpha = __expf(m_i[i] - mnew);
            float rs = 0.f;
#pragma unroll
            for (int j = 0; j < 4; j++) {
                float pv = (s[i][j] > -1e29f) ? __expf(s[i][j] - mnew) : 0.f;
                s[i][j] = pv; rs += pv;
            }
#pragma unroll
            for (int o = 8; o; o >>= 1) rs += __shfl_xor_sync(0xffffffffu, rs, o);
            l_i[i] = l_i[i] * alpha + rs;
            m_i[i] = mnew;
#pragma unroll
            for (int j = 0; j < 16; j++) O[i][j] *= alpha;
            *(float4*)&Ps[((ty<<2)+i)*PADP + (tx<<2)] =
                make_float4(s[i][0], s[i][1], s[i][2], s[i][3]);
        }
        __syncthreads();

#pragma unroll 2
        for (int k = 0; k < BKT; k++) {
            const float* vr = Vs + k*256 + (tx<<4);
            float4 v0 = *(const float4*)(vr + 0);
            float4 v1 = *(const float4*)(vr + 4);
            float4 v2 = *(const float4*)(vr + 8);
            float4 v3 = *(const float4*)(vr + 12);
#pragma unroll
            for (int i = 0; i < 4; i++) {
                float pv = Ps[((ty<<2)+i)*PADP + k];
                O[i][0]  += pv*v0.x; O[i][1]  += pv*v0.y; O[i][2]  += pv*v0.z; O[i][3]  += pv*v0.w;
                O[i][4]  += pv*v1.x; O[i][5]  += pv*v1.y; O[i][6]  += pv*v1.z; O[i][7]  += pv*v1.w;
                O[i][8]  += pv*v2.x; O[i][9]  += pv*v2.y; O[i][10] += pv*v2.z; O[i][11] += pv*v2.w;
                O[i][12] += pv*v3.x; O[i][13] += pv*v3.y; O[i][14] += pv*v3.z; O[i][15] += pv*v3.w;
            }
        }
    }

#pragma unroll
    for (int i = 0; i < 4; i++) {
        float inv = 1.f / l_i[i];
        int q = q0 + (ty<<2) + i;
        float* op = g_att + (size_t)(b*Tseq + q) * ATTN_N + h * Dh + (tx<<4);
        *(float4*)(op + 0)  = make_float4(O[i][0]*inv,  O[i][1]*inv,  O[i][2]*inv,  O[i][3]*inv);
        *(float4*)(op + 4)  = make_float4(O[i][4]*inv,  O[i][5]*inv,  O[i][6]*inv,  O[i][7]*inv);
        *(float4*)(op + 8)  = make_float4(O[i][8]*inv,  O[i][9]*inv,  O[i][10]*inv, O[i][11]*inv);
        *(float4*)(op + 12) = make_float4(O[i][12]*inv, O[i][13]*inv, O[i][14]*inv, O[i][15]*inv);
    }
}

// ---------------- launch ------------------------------------------------------------
extern "C" void kernel_launch(void* const* d_in, const int* in_sizes, int n_in,
                              void* d_out, int out_size) {
    const float* x   = (const float*)d_in[0];
    const float* Wq  = (const float*)d_in[1];
    const float* Wk  = (const float*)d_in[2];
    const float* Wv  = (const float*)d_in[3];
    const float* Wo  = (const float*)d_in[4];
    const float* qsc = (const float*)d_in[5];
    const float* ksc = (const float*)d_in[6];
    const int*   seg = (const int*)d_in[7];
    float* out = (float*)d_out;

    const int* cur;
    if (n_in > 9) cur = (const int*)d_in[9];
    else {
        void* zp; cudaGetSymbolAddress(&zp, g_zero_int);
        cur = (const int*)zp;
    }

    float *qkv, *att;
    cudaGetSymbolAddress((void**)&qkv, g_qkv);
    cudaGetSymbolAddress((void**)&att, g_att);
    float *wqh, *wql, *wkh, *wkl, *wvh, *wvl, *woh, *wol;
    cudaGetSymbolAddress((void**)&wqh, g_wqT_hi); cudaGetSymbolAddress((void**)&wql, g_wqT_lo);
    cudaGetSymbolAddress((void**)&wkh, g_wkT_hi); cudaGetSymbolAddress((void**)&wkl, g_wkT_lo);
    cudaGetSymbolAddress((void**)&wvh, g_wvT_hi); cudaGetSymbolAddress((void**)&wvl, g_wvT_lo);
    cudaGetSymbolAddress((void**)&woh, g_woT_hi); cudaGetSymbolAddress((void**)&wol, g_woT_lo);

    cudaFuncSetAttribute(gemm_mma_kernel, cudaFuncAttributeMaxDynamicSharedMemorySize, GEMM_SMEM);
    size_t asmem = (size_t)(2*256*PADQ + 64*256 + 64*PADP) * sizeof(float);
    cudaFuncSetAttribute(attn_kernel, cudaFuncAttributeMaxDynamicSharedMemorySize, (int)asmem);

    seg_first_kernel<<<Bsz, 256>>>(seg);
    rope_table_kernel<<<ROWS, 128>>>(seg, cur);

    dim3 tb(32, 8);
    transpose_split_kernel<<<dim3(2560/32, 2048/32), tb>>>(Wq, 2560, 2048, wqh, wql);
    transpose_split_kernel<<<dim3(2560/32, 1024/32), tb>>>(Wk, 2560, 1024, wkh, wkl);
    transpose_split_kernel<<<dim3(2560/32, 1024/32), tb>>>(Wv, 2560, 1024, wvh, wvl);
    transpose_split_kernel<<<dim3(2048/32, 2560/32), tb>>>(Wo, 2048, 2560, woh, wol);

    // QKV projections (mma.sync split-tf32)
    gemm_mma_kernel<<<dim3(2048/128, ROWS/128), 256, GEMM_SMEM>>>(x, Hdim, wqh, wql, qkv,        QKVN, Hdim);
    gemm_mma_kernel<<<dim3(1024/128, ROWS/128), 256, GEMM_SMEM>>>(x, Hdim, wkh, wkl, qkv + 2048, QKVN, Hdim);
    gemm_mma_kernel<<<dim3(1024/128, ROWS/128), 256, GEMM_SMEM>>>(x, Hdim, wvh, wvl, qkv + 3072, QKVN, Hdim);

    rmsnorm_rope_kernel<<<ROWS * (NH + NKV), 256>>>(qsc, ksc);

    attn_kernel<<<dim3(Tseq/BQ, NH, Bsz), 256, asmem>>>();

    // output projection
    gemm_mma_kernel<<<dim3(Hdim/128, ROWS/128), 256, GEMM_SMEM>>>(att, ATTN_N, woh, wol, out, Hdim, ATTN_N);
}

// round 4
// speedup vs baseline: 1.4123x; 1.2869x over previous
#include <cuda_runtime.h>
#include <cuda_bf16.h>
#include <math.h>
#include <stdint.h>

#define Bsz    2
#define Tseq   2048
#define Hdim   2560
#define NH     8
#define NKV    4
#define Dh     256
#define WINDOW 1024
#define QKVN   4096          // 2048 q | 1024 k | 1024 v
#define ROWS   (Bsz*Tseq)    // 4096
#define ATTN_N (NH*Dh)       // 2048

// ---------------- scratch (device globals) -----------------------------------
__device__ float g_qkv[(size_t)ROWS * QKVN];   // 64 MB
__device__ float g_att[(size_t)ROWS * ATTN_N]; // 32 MB
__device__ float g_sin[(size_t)ROWS * (Dh/2)];
__device__ float g_cos[(size_t)ROWS * (Dh/2)];
__device__ int   g_first[Bsz];
__device__ int   g_zero_int = 0;

// fragment-major tf32 hi/lo planes
__device__ float g_xf_hi[(size_t)ROWS * Hdim];      // A for QKV gemms
__device__ float g_xf_lo[(size_t)ROWS * Hdim];
__device__ float g_af_hi[(size_t)ROWS * ATTN_N];    // A for Wo gemm
__device__ float g_af_lo[(size_t)ROWS * ATTN_N];
__device__ float g_wq_hi[(size_t)2048 * 2560];
__device__ float g_wq_lo[(size_t)2048 * 2560];
__device__ float g_wk_hi[(size_t)1024 * 2560];
__device__ float g_wk_lo[(size_t)1024 * 2560];
__device__ float g_wv_hi[(size_t)1024 * 2560];
__device__ float g_wv_lo[(size_t)1024 * 2560];
__device__ float g_wo_hi[(size_t)2560 * 2048];
__device__ float g_wo_lo[(size_t)2560 * 2048];

// ---------------- helpers ------------------------------------------------------
__device__ __forceinline__ uint32_t smem_u32(const void* p) {
    uint32_t a;
    asm("{ .reg .u64 t; cvta.to.shared.u64 t, %1; cvt.u32.u64 %0, t; }"
        : "=r"(a) : "l"(p));
    return a;
}
__device__ __forceinline__ float cvt_tf32(float x) {
    float r; asm("cvt.rna.tf32.f32 %0, %1;" : "=f"(r) : "f"(x)); return r;
}
__device__ __forceinline__ void mma_tf32(float* c,
    uint32_t a0, uint32_t a1, uint32_t a2, uint32_t a3,
    uint32_t b0, uint32_t b1)
{
    asm volatile(
        "mma.sync.aligned.m16n8k8.row.col.f32.tf32.tf32.f32 "
        "{%0,%1,%2,%3}, {%4,%5,%6,%7}, {%8,%9}, {%0,%1,%2,%3};"
        : "+f"(c[0]), "+f"(c[1]), "+f"(c[2]), "+f"(c[3])
        : "r"(a0), "r"(a1), "r"(a2), "r"(a3), "r"(b0), "r"(b1));
}
#define CP_ASYNC16(dst, src) \
    asm volatile("cp.async.cg.shared.global [%0], [%1], 16;" :: "r"(dst), "l"(src))
#define CP_COMMIT() asm volatile("cp.async.commit_group;" ::: "memory")
#define CP_WAIT1()  asm volatile("cp.async.wait_group 1;" ::: "memory")

// ---------------- pos helper ----------------------------------------------------
__global__ void seg_first_kernel(const int* __restrict__ seg) {
    __shared__ int smax;
    __shared__ int sidx;
    int b = blockIdx.x, tid = threadIdx.x;
    if (tid == 0) { smax = -2147483647; sidx = 2147483647; }
    __syncthreads();
    int mx = -2147483647;
    for (int t = tid; t < Tseq; t += blockDim.x) mx = max(mx, seg[b*Tseq + t]);
    atomicMax(&smax, mx);
    __syncthreads();
    int mv = smax;
    int mi = 2147483647;
    for (int t = tid; t < Tseq; t += blockDim.x)
        if (seg[b*Tseq + t] == mv) mi = min(mi, t);
    atomicMin(&sidx, mi);
    __syncthreads();
    if (tid == 0) g_first[b] = sidx;
}

// ---------------- rope sin/cos tables --------------------------------------------
__global__ void rope_table_kernel(const int* __restrict__ seg,
                                  const int* __restrict__ cur_ind) {
    int row = blockIdx.x;
    int k   = threadIdx.x;
    int b = row / Tseq, t = row % Tseq;
    int sv = seg[row];
    long long pos = (sv != 0) ? (long long)(t - g_first[b]) : (1ll << 30);
    pos += (long long)cur_ind[0];
    float posf = (float)pos;
    float freq = powf(10000.0f, -((float)(2*k)) / (float)Dh);
    float ang  = posf * freq;
    g_sin[(size_t)row*128 + k] = sinf(ang);
    g_cos[(size_t)row*128 + k] = cosf(ang);
}

// ---------------- pack A (row-major [M][K] -> frag-major hi/lo) -------------------
// A-frag layout: frag[(rb*K8 + k8)*128 + lane*4 + reg]
// reg0:(lr,lc) reg1:(lr+8,lc) reg2:(lr,lc+4) reg3:(lr+8,lc+4), lr=lane>>2, lc=lane&3
__global__ void __launch_bounds__(256) pack_a_kernel(
    const float* __restrict__ A, int K,
    float* __restrict__ Fhi, float* __restrict__ Flo)
{
    __shared__ float tile[16][68];
    int r0 = blockIdx.x * 16, k0 = blockIdx.y * 64;
    int tid = threadIdx.x;
    {
        int row = tid >> 4, q = tid & 15;
        float4 v = *(const float4*)(A + (size_t)(r0 + row) * K + k0 + q*4);
        *(float4*)&tile[row][q*4] = v;
    }
    __syncthreads();
    int k8l = tid >> 5, lane = tid & 31;
    int lr = lane >> 2, lc = lane & 3;
    float v0 = tile[lr    ][k8l*8 + lc    ];
    float v1 = tile[lr + 8][k8l*8 + lc    ];
    float v2 = tile[lr    ][k8l*8 + lc + 4];
    float v3 = tile[lr + 8][k8l*8 + lc + 4];
    float4 h, l;
    h.x = cvt_tf32(v0); l.x = cvt_tf32(v0 - h.x);
    h.y = cvt_tf32(v1); l.y = cvt_tf32(v1 - h.y);
    h.z = cvt_tf32(v2); l.z = cvt_tf32(v2 - h.z);
    h.w = cvt_tf32(v3); l.w = cvt_tf32(v3 - h.w);
    int K8 = K >> 3;
    size_t off = ((size_t)blockIdx.x * K8 + (blockIdx.y*8 + k8l)) * 128 + lane*4;
    *(float4*)(Fhi + off) = h;
    *(float4*)(Flo + off) = l;
}

// ---------------- pack W ([K][N] row-major -> B frag-major hi/lo) -----------------
// B-frag layout: frag[(nb*K8 + k8)*64 + lane*2 + reg]
// reg0:(k=lc,n=lane>>2) reg1:(k=lc+4,n=lane>>2), lc=lane&3
__global__ void __launch_bounds__(256) pack_w_kernel(
    const float* __restrict__ W, int K, int N,
    float* __restrict__ Fhi, float* __restrict__ Flo)
{
    __shared__ float tile[128][9];
    int k0 = blockIdx.x * 128, n0 = blockIdx.y * 8;
    int tid = threadIdx.x;
    {
        int kl = tid >> 1, half = tid & 1;
        float4 v = *(const float4*)(W + (size_t)(k0 + kl) * N + n0 + half*4);
        tile[kl][half*4 + 0] = v.x;
        tile[kl][half*4 + 1] = v.y;
        tile[kl][half*4 + 2] = v.z;
        tile[kl][half*4 + 3] = v.w;
    }
    __syncthreads();
    int k8l = tid >> 4, i = tid & 15;          // lanes 2i, 2i+1
    int K8 = K >> 3;
    float4 h, l;
    {
        int L = 2*i;
        float a = tile[k8l*8 + (L&3)    ][L>>2];
        float b = tile[k8l*8 + (L&3) + 4][L>>2];
        h.x = cvt_tf32(a); l.x = cvt_tf32(a - h.x);
        h.y = cvt_tf32(b); l.y = cvt_tf32(b - h.y);
    }
    {
        int L = 2*i + 1;
        float a = tile[k8l*8 + (L&3)    ][L>>2];
        float b = tile[k8l*8 + (L&3) + 4][L>>2];
        h.z = cvt_tf32(a); l.z = cvt_tf32(a - h.z);
        h.w = cvt_tf32(b); l.w = cvt_tf32(b - h.w);
    }
    size_t off = ((size_t)blockIdx.y * K8 + (blockIdx.x*16 + k8l)) * 64 + i*4;
    *(float4*)(Fhi + off) = h;
    *(float4*)(Flo + off) = l;
}

// ---------------- frag-major split-tf32 GEMM --------------------------------------
// CTA tile 128x128, 8 warps (2M x 4N), warp tile 64x32. K chunk = 32 (4 k8 steps).
// 3-stage cp.async pipeline; stage = Ahi|Alo|Bhi|Blo frags = 64KB.
#define STG_FLT 16384
#define NSTG    3
#define GEMM_SMEM (NSTG * STG_FLT * 4)       // 196608

__global__ void __launch_bounds__(256, 1) gemm_mma_kernel(
    const float* __restrict__ Ahi, const float* __restrict__ Alo,
    const float* __restrict__ Bhi, const float* __restrict__ Blo,
    float* __restrict__ C, int ldc, int K)
{
    extern __shared__ float smf[];
    int tid  = threadIdx.x;
    int lane = tid & 31, wid = tid >> 5;
    int wm = wid >> 2, wn = wid & 3;
    int m0 = blockIdx.y * 128, n0 = blockIdx.x * 128;
    int K8 = K >> 3;
    int rb0 = m0 >> 4, nb0 = n0 >> 3;
    const int nc = K >> 5;

    // per-thread loader constants (16 x 16B per chunk)
    int region = tid >> 6;           // 0..3 over i-major? recompute inside loop instead
    (void)region;

    float acc[4][4][4];
#pragma unroll
    for (int i = 0; i < 4; i++)
#pragma unroll
        for (int j = 0; j < 4; j++)
#pragma unroll
            for (int r = 0; r < 4; r++) acc[i][j][r] = 0.f;

    uint32_t sbase = smem_u32(smf);

    // issue one chunk's copies into stage s
    auto issue = [&](int c, int s) {
        uint32_t sd = sbase + s * (STG_FLT * 4);
        int c4 = c * 4;
#pragma unroll
        for (int i = 0; i < 16; i++) {
            int idx = tid + i * 256;
            int reg = idx >> 10, sub = idx & 1023;
            const float* src;
            if (reg < 2) {
                int rb = sub >> 7, k8 = (sub >> 5) & 3, j = sub & 31;
                const float* pl = reg ? Alo : Ahi;
                src = pl + ((size_t)(rb0 + rb) * K8 + c4 + k8) * 128 + j*4;
            } else {
                int nb = sub >> 6, k8 = (sub >> 4) & 3, j = sub & 15;
                const float* pl = (reg == 3) ? Blo : Bhi;
                src = pl + ((size_t)(nb0 + nb) * K8 + c4 + k8) * 64 + j*4;
            }
            CP_ASYNC16(sd + idx * 16, src);
        }
    };

    issue(0, 0); CP_COMMIT();
    if (nc > 1) issue(1, 1);
    CP_COMMIT();

    for (int c = 0; c < nc; c++) {
        CP_WAIT1();
        __syncthreads();

        const float* sA = smf + (c % NSTG) * STG_FLT;
        const float* pA = sA + (wm * 16) * 128 + lane * 4;
        const float* pB = sA + 8192 + (wn * 16) * 64 + lane * 2;

#pragma unroll
        for (int k8 = 0; k8 < 4; k8++) {
            uint4 AH[4], AL[4];
            uint2 BH[4], BL[4];
#pragma unroll
            for (int mt = 0; mt < 4; mt++) {
                AH[mt] = *(const uint4*)(pA + (mt*4 + k8) * 128);
                AL[mt] = *(const uint4*)(pA + 4096 + (mt*4 + k8) * 128);
            }
#pragma unroll
            for (int nt = 0; nt < 4; nt++) {
                BH[nt] = *(const uint2*)(pB + (nt*4 + k8) * 64);
                BL[nt] = *(const uint2*)(pB + 4096 + (nt*4 + k8) * 64);
            }
#pragma unroll
            for (int mt = 0; mt < 4; mt++)
#pragma unroll
                for (int nt = 0; nt < 4; nt++) {
                    float* cc = acc[mt][nt];
                    mma_tf32(cc, AH[mt].x, AH[mt].y, AH[mt].z, AH[mt].w,
                             BH[nt].x, BH[nt].y);
                    mma_tf32(cc, AL[mt].x, AL[mt].y, AL[mt].z, AL[mt].w,
                             BH[nt].x, BH[nt].y);
                    mma_tf32(cc, AH[mt].x, AH[mt].y, AH[mt].z, AH[mt].w,
                             BL[nt].x, BL[nt].y);
                }
        }

        if (c + 2 < nc) issue(c + 2, (c + 2) % NSTG);
        CP_COMMIT();
    }

    // epilogue
#pragma unroll
    for (int mt = 0; mt < 4; mt++) {
        int row0 = m0 + wm*64 + mt*16 + (lane >> 2);
#pragma unroll
        for (int nt = 0; nt < 4; nt++) {
            int col = n0 + wn*32 + nt*8 + 2*(lane & 3);
            float* cc = acc[mt][nt];
            *(float2*)(C + (size_t)row0 * ldc + col)       = make_float2(cc[0], cc[1]);
            *(float2*)(C + (size_t)(row0 + 8) * ldc + col) = make_float2(cc[2], cc[3]);
        }
    }
}

// ---------------- RMSNorm + RoPE in place on q/k columns --------------------------
__global__ void __launch_bounds__(256) rmsnorm_rope_kernel(
    const float* __restrict__ qsc, const float* __restrict__ ksc)
{
    int bid = blockIdx.x;
    int row = bid / (NH + NKV);
    int hi  = bid % (NH + NKV);
    int off; const float* sc;
    if (hi < NH) { off = hi * Dh;               sc = qsc; }
    else         { off = NH*Dh + (hi-NH) * Dh;  sc = ksc; }
    float* p = g_qkv + (size_t)row * QKVN + off;
    int tid = threadIdx.x;
    float x = p[tid];
    float ss = x * x;
#pragma unroll
    for (int o = 16; o; o >>= 1) ss += __shfl_xor_sync(0xffffffffu, ss, o);
    __shared__ float red[8];
    __shared__ float tot;
    __shared__ float sy[256];
    if ((tid & 31) == 0) red[tid >> 5] = ss;
    __syncthreads();
    if (tid == 0) {
        float t = 0.f;
        for (int i = 0; i < 8; i++) t += red[i];
        tot = t;
    }
    __syncthreads();
    float rms = rsqrtf(tot * (1.0f / Dh) + 1e-6f);
    float y = x * rms * (1.0f + sc[tid]);
    sy[tid] = y;
    __syncthreads();
    int kidx = tid & 127;
    float s_ = g_sin[(size_t)row*128 + kidx];
    float c_ = g_cos[(size_t)row*128 + kidx];
    float out;
    if (tid < 128) out = y * c_ - sy[tid + 128] * s_;
    else           out = y * c_ + sy[tid - 128] * s_;
    p[tid] = out;
}

// ---------------- flash attention (fp32, sliding window, GQA) ---------------------
#define BQ    64
#define BKT   64
#define PADQ  65
#define PADP  68
#define SM_SCALE 0.0625f

__global__ void __launch_bounds__(256) attn_kernel() {
    extern __shared__ float smd[];
    float* Qs = smd;
    float* Ks = Qs + 256 * PADQ;
    float* Vs = Ks + 256 * PADQ;
    float* Ps = Vs + 64 * 256;
    int q0 = blockIdx.x * BQ;
    int h  = blockIdx.y, b = blockIdx.z;
    int tid = threadIdx.x;
    int tx = tid & 15, ty = tid >> 4;
    int kvh = h >> 1;
    const float* baseq = g_qkv + (size_t)b * Tseq * QKVN + h * Dh;
    const float* basek = g_qkv + (size_t)b * Tseq * QKVN + NH*Dh + kvh * Dh;
    const float* basev = g_qkv + (size_t)b * Tseq * QKVN + NH*Dh + NKV*Dh + kvh * Dh;

    {
        int dg = tid & 15, r = tid >> 4;
#pragma unroll
        for (int it = 0; it < 4; it++) {
            int d0 = (it*16 + dg) * 4;
#pragma unroll
            for (int kit = 0; kit < 4; kit++) {
                int qr = r + kit*16;
                float4 v = *(const float4*)(baseq + (size_t)(q0+qr)*QKVN + d0);
                Qs[(d0+0)*PADQ + qr] = v.x;
                Qs[(d0+1)*PADQ + qr] = v.y;
                Qs[(d0+2)*PADQ + qr] = v.z;
                Qs[(d0+3)*PADQ + qr] = v.w;
            }
        }
    }

    float m_i[4], l_i[4], O[4][16];
#pragma unroll
    for (int i = 0; i < 4; i++) {
        m_i[i] = -1e30f; l_i[i] = 0.f;
#pragma unroll
        for (int j = 0; j < 16; j++) O[i][j] = 0.f;
    }

    int kstart = q0 - (WINDOW - 1); if (kstart < 0) kstart = 0;
    int kt0 = kstart & ~(BKT - 1);

    for (int kt = kt0; kt < q0 + BQ; kt += BKT) {
        __syncthreads();
        {
            int dg = tid & 15, r = tid >> 4;
#pragma unroll
            for (int it = 0; it < 4; it++) {
                int d0 = (it*16 + dg) * 4;
#pragma unroll
                for (int kit = 0; kit < 4; kit++) {
                    int kr = r + kit*16;
                    float4 v = *(const float4*)(basek + (size_t)(kt+kr)*QKVN + d0);
                    Ks[(d0+0)*PADQ + kr] = v.x;
                    Ks[(d0+1)*PADQ + kr] = v.y;
                    Ks[(d0+2)*PADQ + kr] = v.z;
                    Ks[(d0+3)*PADQ + kr] = v.w;
                }
            }
#pragma unroll
            for (int c = 0; c < 16; c++) {
                int fidx = tid + c*256;
                int kr = fidx >> 6, d4 = (fidx & 63) << 2;
                *(float4*)&Vs[kr*256 + d4] =
                    *(const float4*)(basev + (size_t)(kt+kr)*QKVN + d4);
            }
        }
        __syncthreads();

        float s[4][4];
#pragma unroll
        for (int i = 0; i < 4; i++)
#pragma unroll
            for (int j = 0; j < 4; j++) s[i][j] = 0.f;
        const float* qp = Qs + (ty << 2);
        const float* kp = Ks + (tx << 2);
#pragma unroll 4
        for (int d = 0; d < 256; d++) {
            float a0 = qp[d*PADQ+0], a1 = qp[d*PADQ+1], a2 = qp[d*PADQ+2], a3 = qp[d*PADQ+3];
            float b0 = kp[d*PADQ+0], b1 = kp[d*PADQ+1], b2 = kp[d*PADQ+2], b3 = kp[d*PADQ+3];
            s[0][0] += a0*b0; s[0][1] += a0*b1; s[0][2] += a0*b2; s[0][3] += a0*b3;
            s[1][0] += a1*b0; s[1][1] += a1*b1; s[1][2] += a1*b2; s[1][3] += a1*b3;
            s[2][0] += a2*b0; s[2][1] += a2*b1; s[2][2] += a2*b2; s[2][3] += a2*b3;
            s[3][0] += a3*b0; s[3][1] += a3*b1; s[3][2] += a3*b2; s[3][3] += a3*b3;
        }

#pragma unroll
        for (int i = 0; i < 4; i++) {
            int qg = q0 + (ty<<2) + i;
            float mx = -1e30f;
#pragma unroll
            for (int j = 0; j < 4; j++) {
                int kg = kt + (tx<<2) + j;
                float sv = s[i][j] * SM_SCALE;
                bool valid = (kg <= qg) && (qg - kg < WINDOW);
                sv = valid ? sv : -1e30f;
                s[i][j] = sv;
                mx = fmaxf(mx, sv);
            }
#pragma unroll
            for (int o = 8; o; o >>= 1) mx = fmaxf(mx, __shfl_xor_sync(0xffffffffu, mx, o));
            float mnew  = fmaxf(m_i[i], mx);
            float alpha = __expf(m_i[i] - mnew);
            float rs = 0.f;
#pragma unroll
            for (int j = 0; j < 4; j++) {
                float pv = (s[i][j] > -1e29f) ? __expf(s[i][j] - mnew) : 0.f;
                s[i][j] = pv; rs += pv;
            }
#pragma unroll
            for (int o = 8; o; o >>= 1) rs += __shfl_xor_sync(0xffffffffu, rs, o);
            l_i[i] = l_i[i] * alpha + rs;
            m_i[i] = mnew;
#pragma unroll
            for (int j = 0; j < 16; j++) O[i][j] *= alpha;
            *(float4*)&Ps[((ty<<2)+i)*PADP + (tx<<2)] =
                make_float4(s[i][0], s[i][1], s[i][2], s[i][3]);
        }
        __syncthreads();

#pragma unroll 2
        for (int k = 0; k < BKT; k++) {
            const float* vr = Vs + k*256 + (tx<<4);
            float4 v0 = *(const float4*)(vr + 0);
            float4 v1 = *(const float4*)(vr + 4);
            float4 v2 = *(const float4*)(vr + 8);
            float4 v3 = *(const float4*)(vr + 12);
#pragma unroll
            for (int i = 0; i < 4; i++) {
                float pv = Ps[((ty<<2)+i)*PADP + k];
                O[i][0]  += pv*v0.x; O[i][1]  += pv*v0.y; O[i][2]  += pv*v0.z; O[i][3]  += pv*v0.w;
                O[i][4]  += pv*v1.x; O[i][5]  += pv*v1.y; O[i][6]  += pv*v1.z; O[i][7]  += pv*v1.w;
                O[i][8]  += pv*v2.x; O[i][9]  += pv*v2.y; O[i][10] += pv*v2.z; O[i][11] += pv*v2.w;
                O[i][12] += pv*v3.x; O[i][13] += pv*v3.y; O[i][14] += pv*v3.z; O[i][15] += pv*v3.w;
            }
        }
    }

#pragma unroll
    for (int i = 0; i < 4; i++) {
        float inv = 1.f / l_i[i];
        int q = q0 + (ty<<2) + i;
        float* op = g_att + (size_t)(b*Tseq + q) * ATTN_N + h * Dh + (tx<<4);
        *(float4*)(op + 0)  = make_float4(O[i][0]*inv,  O[i][1]*inv,  O[i][2]*inv,  O[i][3]*inv);
        *(float4*)(op + 4)  = make_float4(O[i][4]*inv,  O[i][5]*inv,  O[i][6]*inv,  O[i][7]*inv);
        *(float4*)(op + 8)  = make_float4(O[i][8]*inv,  O[i][9]*inv,  O[i][10]*inv, O[i][11]*inv);
        *(float4*)(op + 12) = make_float4(O[i][12]*inv, O[i][13]*inv, O[i][14]*inv, O[i][15]*inv);
    }
}

// ---------------- launch ------------------------------------------------------------
extern "C" void kernel_launch(void* const* d_in, const int* in_sizes, int n_in,
                              void* d_out, int out_size) {
    const float* x   = (const float*)d_in[0];
    const float* Wq  = (const float*)d_in[1];
    const float* Wk  = (const float*)d_in[2];
    const float* Wv  = (const float*)d_in[3];
    const float* Wo  = (const float*)d_in[4];
    const float* qsc = (const float*)d_in[5];
    const float* ksc = (const float*)d_in[6];
    const int*   seg = (const int*)d_in[7];
    float* out = (float*)d_out;

    const int* cur;
    if (n_in > 9) cur = (const int*)d_in[9];
    else {
        void* zp; cudaGetSymbolAddress(&zp, g_zero_int);
        cur = (const int*)zp;
    }

    float *qkv, *att;
    cudaGetSymbolAddress((void**)&qkv, g_qkv);
    cudaGetSymbolAddress((void**)&att, g_att);
    float *xfh, *xfl, *afh, *afl;
    cudaGetSymbolAddress((void**)&xfh, g_xf_hi); cudaGetSymbolAddress((void**)&xfl, g_xf_lo);
    cudaGetSymbolAddress((void**)&afh, g_af_hi); cudaGetSymbolAddress((void**)&afl, g_af_lo);
    float *wqh, *wql, *wkh, *wkl, *wvh, *wvl, *woh, *wol;
    cudaGetSymbolAddress((void**)&wqh, g_wq_hi); cudaGetSymbolAddress((void**)&wql, g_wq_lo);
    cudaGetSymbolAddress((void**)&wkh, g_wk_hi); cudaGetSymbolAddress((void**)&wkl, g_wk_lo);
    cudaGetSymbolAddress((void**)&wvh, g_wv_hi); cudaGetSymbolAddress((void**)&wvl, g_wv_lo);
    cudaGetSymbolAddress((void**)&woh, g_wo_hi); cudaGetSymbolAddress((void**)&wol, g_wo_lo);

    cudaFuncSetAttribute(gemm_mma_kernel, cudaFuncAttributeMaxDynamicSharedMemorySize, GEMM_SMEM);
    size_t asmem = (size_t)(2*256*PADQ + 64*256 + 64*PADP) * sizeof(float);
    cudaFuncSetAttribute(attn_kernel, cudaFuncAttributeMaxDynamicSharedMemorySize, (int)asmem);

    seg_first_kernel<<<Bsz, 256>>>(seg);
    rope_table_kernel<<<ROWS, 128>>>(seg, cur);

    // pack operands
    pack_a_kernel<<<dim3(ROWS/16, Hdim/64), 256>>>(x, Hdim, xfh, xfl);
    pack_w_kernel<<<dim3(2560/128, 2048/8), 256>>>(Wq, 2560, 2048, wqh, wql);
    pack_w_kernel<<<dim3(2560/128, 1024/8), 256>>>(Wk, 2560, 1024, wkh, wkl);
    pack_w_kernel<<<dim3(2560/128, 1024/8), 256>>>(Wv, 2560, 1024, wvh, wvl);
    pack_w_kernel<<<dim3(2048/128, 2560/8), 256>>>(Wo, 2048, 2560, woh, wol);

    // QKV projections
    gemm_mma_kernel<<<dim3(2048/128, ROWS/128), 256, GEMM_SMEM>>>(xfh, xfl, wqh, wql, qkv,        QKVN, Hdim);
    gemm_mma_kernel<<<dim3(1024/128, ROWS/128), 256, GEMM_SMEM>>>(xfh, xfl, wkh, wkl, qkv + 2048, QKVN, Hdim);
    gemm_mma_kernel<<<dim3(1024/128, ROWS/128), 256, GEMM_SMEM>>>(xfh, xfl, wvh, wvl, qkv + 3072, QKVN, Hdim);

    rmsnorm_rope_kernel<<<ROWS * (NH + NKV), 256>>>(qsc, ksc);

    attn_kernel<<<dim3(Tseq/BQ, NH, Bsz), 256, asmem>>>();

    // pack attention output, then output projection
    pack_a_kernel<<<dim3(ROWS/16, ATTN_N/64), 256>>>(att, ATTN_N, afh, afl);
    gemm_mma_kernel<<<dim3(Hdim/128, ROWS/128), 256, GEMM_SMEM>>>(afh, afl, woh, wol, out, Hdim, ATTN_N);
}

// round 5
// speedup vs baseline: 2.1589x; 1.5287x over previous
#include <cuda_runtime.h>
#include <cuda_bf16.h>
#include <math.h>
#include <stdint.h>

#define Bsz    2
#define Tseq   2048
#define Hdim   2560
#define NH     8
#define NKV    4
#define Dh     256
#define WINDOW 1024
#define QKVN   4096          // 2048 q | 1024 k | 1024 v
#define ROWS   (Bsz*Tseq)    // 4096
#define ATTN_N (NH*Dh)       // 2048

// ---------------- scratch (device globals) -----------------------------------
__device__ float g_qkv[(size_t)ROWS * QKVN];   // 64 MB
__device__ float g_att[(size_t)ROWS * ATTN_N]; // 32 MB
__device__ float g_sin[(size_t)ROWS * (Dh/2)];
__device__ float g_cos[(size_t)ROWS * (Dh/2)];
__device__ int   g_first[Bsz];
__device__ int   g_zero_int = 0;

// fragment-major tf32 hi/lo planes
__device__ float g_xf_hi[(size_t)ROWS * Hdim];
__device__ float g_xf_lo[(size_t)ROWS * Hdim];
__device__ float g_af_hi[(size_t)ROWS * ATTN_N];
__device__ float g_af_lo[(size_t)ROWS * ATTN_N];
__device__ float g_wq_hi[(size_t)2048 * 2560];
__device__ float g_wq_lo[(size_t)2048 * 2560];
__device__ float g_wk_hi[(size_t)1024 * 2560];
__device__ float g_wk_lo[(size_t)1024 * 2560];
__device__ float g_wv_hi[(size_t)1024 * 2560];
__device__ float g_wv_lo[(size_t)1024 * 2560];
__device__ float g_wo_hi[(size_t)2560 * 2048];
__device__ float g_wo_lo[(size_t)2560 * 2048];

// ---------------- helpers ------------------------------------------------------
__device__ __forceinline__ uint32_t smem_u32(const void* p) {
    uint32_t a;
    asm("{ .reg .u64 t; cvta.to.shared.u64 t, %1; cvt.u32.u64 %0, t; }"
        : "=r"(a) : "l"(p));
    return a;
}
__device__ __forceinline__ float cvt_tf32(float x) {
    float r; asm("cvt.rna.tf32.f32 %0, %1;" : "=f"(r) : "f"(x)); return r;
}
__device__ __forceinline__ void mma_tf32(float* c,
    uint32_t a0, uint32_t a1, uint32_t a2, uint32_t a3,
    uint32_t b0, uint32_t b1)
{
    asm volatile(
        "mma.sync.aligned.m16n8k8.row.col.f32.tf32.tf32.f32 "
        "{%0,%1,%2,%3}, {%4,%5,%6,%7}, {%8,%9}, {%0,%1,%2,%3};"
        : "+f"(c[0]), "+f"(c[1]), "+f"(c[2]), "+f"(c[3])
        : "r"(a0), "r"(a1), "r"(a2), "r"(a3), "r"(b0), "r"(b1));
}
__device__ __forceinline__ void ldsm_x4(uint32_t& r0, uint32_t& r1,
                                        uint32_t& r2, uint32_t& r3, uint32_t addr)
{
    asm volatile("ldmatrix.sync.aligned.m8n8.x4.shared.b16 {%0,%1,%2,%3}, [%4];"
        : "=r"(r0), "=r"(r1), "=r"(r2), "=r"(r3) : "r"(addr));
}
#define CP_ASYNC16(dst, src) \
    asm volatile("cp.async.cg.shared.global [%0], [%1], 16;" :: "r"(dst), "l"(src))
#define CP_COMMIT()   asm volatile("cp.async.commit_group;" ::: "memory")
#define CP_WAIT1()    asm volatile("cp.async.wait_group 1;" ::: "memory")
#define CP_WAIT_ALL() asm volatile("cp.async.wait_group 0;" ::: "memory")

// ---------------- pos helper ----------------------------------------------------
__global__ void seg_first_kernel(const int* __restrict__ seg) {
    __shared__ int smax;
    __shared__ int sidx;
    int b = blockIdx.x, tid = threadIdx.x;
    if (tid == 0) { smax = -2147483647; sidx = 2147483647; }
    __syncthreads();
    int mx = -2147483647;
    for (int t = tid; t < Tseq; t += blockDim.x) mx = max(mx, seg[b*Tseq + t]);
    atomicMax(&smax, mx);
    __syncthreads();
    int mv = smax;
    int mi = 2147483647;
    for (int t = tid; t < Tseq; t += blockDim.x)
        if (seg[b*Tseq + t] == mv) mi = min(mi, t);
    atomicMin(&sidx, mi);
    __syncthreads();
    if (tid == 0) g_first[b] = sidx;
}

// ---------------- rope sin/cos tables --------------------------------------------
__global__ void rope_table_kernel(const int* __restrict__ seg,
                                  const int* __restrict__ cur_ind) {
    int row = blockIdx.x;
    int k   = threadIdx.x;
    int b = row / Tseq, t = row % Tseq;
    int sv = seg[row];
    long long pos = (sv != 0) ? (long long)(t - g_first[b]) : (1ll << 30);
    pos += (long long)cur_ind[0];
    float posf = (float)pos;
    float freq = powf(10000.0f, -((float)(2*k)) / (float)Dh);
    float ang  = posf * freq;
    g_sin[(size_t)row*128 + k] = sinf(ang);
    g_cos[(size_t)row*128 + k] = cosf(ang);
}

// ---------------- pack A (row-major [M][K] -> frag-major hi/lo) -------------------
__global__ void __launch_bounds__(256) pack_a_kernel(
    const float* __restrict__ A, int K,
    float* __restrict__ Fhi, float* __restrict__ Flo)
{
    __shared__ float tile[16][68];
    int r0 = blockIdx.x * 16, k0 = blockIdx.y * 64;
    int tid = threadIdx.x;
    {
        int row = tid >> 4, q = tid & 15;
        float4 v = *(const float4*)(A + (size_t)(r0 + row) * K + k0 + q*4);
        *(float4*)&tile[row][q*4] = v;
    }
    __syncthreads();
    int k8l = tid >> 5, lane = tid & 31;
    int lr = lane >> 2, lc = lane & 3;
    float v0 = tile[lr    ][k8l*8 + lc    ];
    float v1 = tile[lr + 8][k8l*8 + lc    ];
    float v2 = tile[lr    ][k8l*8 + lc + 4];
    float v3 = tile[lr + 8][k8l*8 + lc + 4];
    float4 h, l;
    h.x = cvt_tf32(v0); l.x = cvt_tf32(v0 - h.x);
    h.y = cvt_tf32(v1); l.y = cvt_tf32(v1 - h.y);
    h.z = cvt_tf32(v2); l.z = cvt_tf32(v2 - h.z);
    h.w = cvt_tf32(v3); l.w = cvt_tf32(v3 - h.w);
    int K8 = K >> 3;
    size_t off = ((size_t)blockIdx.x * K8 + (blockIdx.y*8 + k8l)) * 128 + lane*4;
    *(float4*)(Fhi + off) = h;
    *(float4*)(Flo + off) = l;
}

// ---------------- pack W ([K][N] row-major -> B frag-major hi/lo) -----------------
__global__ void __launch_bounds__(256) pack_w_kernel(
    const float* __restrict__ W, int K, int N,
    float* __restrict__ Fhi, float* __restrict__ Flo)
{
    __shared__ float tile[128][9];
    int k0 = blockIdx.x * 128, n0 = blockIdx.y * 8;
    int tid = threadIdx.x;
    {
        int kl = tid >> 1, half = tid & 1;
        float4 v = *(const float4*)(W + (size_t)(k0 + kl) * N + n0 + half*4);
        tile[kl][half*4 + 0] = v.x;
        tile[kl][half*4 + 1] = v.y;
        tile[kl][half*4 + 2] = v.z;
        tile[kl][half*4 + 3] = v.w;
    }
    __syncthreads();
    int k8l = tid >> 4, i = tid & 15;
    int K8 = K >> 3;
    float4 h, l;
    {
        int L = 2*i;
        float a = tile[k8l*8 + (L&3)    ][L>>2];
        float b = tile[k8l*8 + (L&3) + 4][L>>2];
        h.x = cvt_tf32(a); l.x = cvt_tf32(a - h.x);
        h.y = cvt_tf32(b); l.y = cvt_tf32(b - h.y);
    }
    {
        int L = 2*i + 1;
        float a = tile[k8l*8 + (L&3)    ][L>>2];
        float b = tile[k8l*8 + (L&3) + 4][L>>2];
        h.z = cvt_tf32(a); l.z = cvt_tf32(a - h.z);
        h.w = cvt_tf32(b); l.w = cvt_tf32(b - h.w);
    }
    size_t off = ((size_t)blockIdx.y * K8 + (blockIdx.x*16 + k8l)) * 64 + i*4;
    *(float4*)(Fhi + off) = h;
    *(float4*)(Flo + off) = l;
}

// ---------------- frag-major split-tf32 GEMM --------------------------------------
#define STG_FLT 16384
#define NSTG    3
#define GEMM_SMEM (NSTG * STG_FLT * 4)

__global__ void __launch_bounds__(256, 1) gemm_mma_kernel(
    const float* __restrict__ Ahi, const float* __restrict__ Alo,
    const float* __restrict__ Bhi, const float* __restrict__ Blo,
    float* __restrict__ C, int ldc, int K)
{
    extern __shared__ float smf[];
    int tid  = threadIdx.x;
    int lane = tid & 31, wid = tid >> 5;
    int wm = wid >> 2, wn = wid & 3;
    int m0 = blockIdx.y * 128, n0 = blockIdx.x * 128;
    int K8 = K >> 3;
    int rb0 = m0 >> 4, nb0 = n0 >> 3;
    const int nc = K >> 5;

    float acc[4][4][4];
#pragma unroll
    for (int i = 0; i < 4; i++)
#pragma unroll
        for (int j = 0; j < 4; j++)
#pragma unroll
            for (int r = 0; r < 4; r++) acc[i][j][r] = 0.f;

    uint32_t sbase = smem_u32(smf);

    auto issue = [&](int c, int s) {
        uint32_t sd = sbase + s * (STG_FLT * 4);
        int c4 = c * 4;
#pragma unroll
        for (int i = 0; i < 16; i++) {
            int idx = tid + i * 256;
            int reg = idx >> 10, sub = idx & 1023;
            const float* src;
            if (reg < 2) {
                int rb = sub >> 7, k8 = (sub >> 5) & 3, j = sub & 31;
                const float* pl = reg ? Alo : Ahi;
                src = pl + ((size_t)(rb0 + rb) * K8 + c4 + k8) * 128 + j*4;
            } else {
                int nb = sub >> 6, k8 = (sub >> 4) & 3, j = sub & 15;
                const float* pl = (reg == 3) ? Blo : Bhi;
                src = pl + ((size_t)(nb0 + nb) * K8 + c4 + k8) * 64 + j*4;
            }
            CP_ASYNC16(sd + idx * 16, src);
        }
    };

    issue(0, 0); CP_COMMIT();
    if (nc > 1) issue(1, 1);
    CP_COMMIT();

    for (int c = 0; c < nc; c++) {
        CP_WAIT1();
        __syncthreads();

        const float* sA = smf + (c % NSTG) * STG_FLT;
        const float* pA = sA + (wm * 16) * 128 + lane * 4;
        const float* pB = sA + 8192 + (wn * 16) * 64 + lane * 2;

#pragma unroll
        for (int k8 = 0; k8 < 4; k8++) {
            uint4 AH[4], AL[4];
            uint2 BH[4], BL[4];
#pragma unroll
            for (int mt = 0; mt < 4; mt++) {
                AH[mt] = *(const uint4*)(pA + (mt*4 + k8) * 128);
                AL[mt] = *(const uint4*)(pA + 4096 + (mt*4 + k8) * 128);
            }
#pragma unroll
            for (int nt = 0; nt < 4; nt++) {
                BH[nt] = *(const uint2*)(pB + (nt*4 + k8) * 64);
                BL[nt] = *(const uint2*)(pB + 4096 + (nt*4 + k8) * 64);
            }
#pragma unroll
            for (int mt = 0; mt < 4; mt++)
#pragma unroll
                for (int nt = 0; nt < 4; nt++) {
                    float* cc = acc[mt][nt];
                    mma_tf32(cc, AH[mt].x, AH[mt].y, AH[mt].z, AH[mt].w,
                             BH[nt].x, BH[nt].y);
                    mma_tf32(cc, AL[mt].x, AL[mt].y, AL[mt].z, AL[mt].w,
                             BH[nt].x, BH[nt].y);
                    mma_tf32(cc, AH[mt].x, AH[mt].y, AH[mt].z, AH[mt].w,
                             BL[nt].x, BL[nt].y);
                }
        }

        if (c + 2 < nc) issue(c + 2, (c + 2) % NSTG);
        CP_COMMIT();
    }

#pragma unroll
    for (int mt = 0; mt < 4; mt++) {
        int row0 = m0 + wm*64 + mt*16 + (lane >> 2);
#pragma unroll
        for (int nt = 0; nt < 4; nt++) {
            int col = n0 + wn*32 + nt*8 + 2*(lane & 3);
            float* cc = acc[mt][nt];
            *(float2*)(C + (size_t)row0 * ldc + col)       = make_float2(cc[0], cc[1]);
            *(float2*)(C + (size_t)(row0 + 8) * ldc + col) = make_float2(cc[2], cc[3]);
        }
    }
}

// ---------------- RMSNorm + RoPE (q,k) + tf32 rounding (q,k,v) --------------------
// grid = ROWS * 16: hi<8 -> q head, 8..11 -> k head, 12..15 -> v head (cvt only)
__global__ void __launch_bounds__(256) rmsnorm_rope_kernel(
    const float* __restrict__ qsc, const float* __restrict__ ksc)
{
    int bid = blockIdx.x;
    int row = bid >> 4;
    int hi  = bid & 15;
    int tid = threadIdx.x;
    if (hi >= 12) {
        float* p = g_qkv + (size_t)row * QKVN + NH*Dh + NKV*Dh + (hi-12) * Dh;
        p[tid] = cvt_tf32(p[tid]);
        return;
    }
    int off; const float* sc;
    if (hi < NH) { off = hi * Dh;              sc = qsc; }
    else         { off = NH*Dh + (hi-NH) * Dh; sc = ksc; }
    float* p = g_qkv + (size_t)row * QKVN + off;
    float x = p[tid];
    float ss = x * x;
#pragma unroll
    for (int o = 16; o; o >>= 1) ss += __shfl_xor_sync(0xffffffffu, ss, o);
    __shared__ float red[8];
    __shared__ float tot;
    __shared__ float sy[256];
    if ((tid & 31) == 0) red[tid >> 5] = ss;
    __syncthreads();
    if (tid == 0) {
        float t = 0.f;
        for (int i = 0; i < 8; i++) t += red[i];
        tot = t;
    }
    __syncthreads();
    float rms = rsqrtf(tot * (1.0f / Dh) + 1e-6f);
    float y = x * rms * (1.0f + sc[tid]);
    sy[tid] = y;
    __syncthreads();
    int kidx = tid & 127;
    float s_ = g_sin[(size_t)row*128 + kidx];
    float c_ = g_cos[(size_t)row*128 + kidx];
    float out;
    if (tid < 128) out = y * c_ - sy[tid + 128] * s_;
    else           out = y * c_ + sy[tid - 128] * s_;
    p[tid] = cvt_tf32(out);
}

// ---------------- tensor-core flash attention -------------------------------------
// BQ=64, BKT=32, 8 warps: wm=wid>>1 (q rows 16*wm..+16), wn=wid&1 (halves).
// S warp tile 16x16 (2 n8 blocks), O warp tile 16x128 (16 n8 blocks).
#define ABK       32
#define QS_STR    260
#define KS_STR    260
#define VS_STR    264
#define PS_STR    36
#define QS_OFF    0
#define KS_OFF    16640                 // 64*260
#define KS_STG    8320                  // 32*260
#define VS_OFF    (KS_OFF + 2*KS_STG)   // 33280
#define VS_STG    8448                  // 32*264
#define PS_OFF    (VS_OFF + 2*VS_STG)   // 50176
#define RED_OFF   (PS_OFF + 64*PS_STR)  // 52480
#define SUM_OFF   (RED_OFF + 128)       // 52608
#define ATTN_SMEM ((SUM_OFF + 128) * 4) // 210944 bytes
#define SM_SCALE  0.0625f

__global__ void __launch_bounds__(256, 1) attn_mma_kernel() {
    extern __shared__ float smf[];
    uint32_t sb = smem_u32(smf);
    int tid  = threadIdx.x;
    int lane = tid & 31, wid = tid >> 5;
    int lr = lane >> 2, lc = lane & 3;
    int wm = wid >> 1, wn = wid & 1;

    int q0 = blockIdx.x * 64;
    int h  = blockIdx.y, b = blockIdx.z;
    int kvh = h >> 1;
    const float* baseq = g_qkv + (size_t)b * Tseq * QKVN + h * Dh;
    const float* basek = g_qkv + (size_t)b * Tseq * QKVN + NH*Dh + kvh * Dh;
    const float* basev = g_qkv + (size_t)b * Tseq * QKVN + NH*Dh + NKV*Dh + kvh * Dh;

    // cp.async issue: Q tile (once), K/V tile (per k-tile)
    auto issueQ = [&]() {
#pragma unroll
        for (int i = 0; i < 16; i++) {
            int idx = tid + i * 256;
            int r = idx >> 6, c = idx & 63;
            CP_ASYNC16(sb + (QS_OFF + r*QS_STR + c*4) * 4,
                       baseq + (size_t)(q0 + r) * QKVN + c*4);
        }
    };
    auto issueKV = [&](int kt, int s) {
#pragma unroll
        for (int i = 0; i < 8; i++) {
            int idx = tid + i * 256;
            int r = idx >> 6, c = idx & 63;
            CP_ASYNC16(sb + (KS_OFF + s*KS_STG + r*KS_STR + c*4) * 4,
                       basek + (size_t)(kt + r) * QKVN + c*4);
        }
#pragma unroll
        for (int i = 0; i < 8; i++) {
            int idx = tid + i * 256;
            int r = idx >> 6, c = idx & 63;
            CP_ASYNC16(sb + (VS_OFF + s*VS_STG + r*VS_STR + c*4) * 4,
                       basev + (size_t)(kt + r) * QKVN + c*4);
        }
    };

    int kstart = q0 - (WINDOW - 1); if (kstart < 0) kstart = 0;
    int kt0 = kstart & ~(ABK - 1);
    int nt  = (q0 + 64 - kt0) >> 5;

    issueQ();
    issueKV(kt0, 0);
    CP_COMMIT();

    // ldmatrix lane addresses (A frags from Qs and Ps)
    int arow = 16*wm + (lane & 7) + ((lane >> 3) & 1) * 8;
    int acol = (lane >> 4) * 4;
    uint32_t qs_addr = sb + (QS_OFF + arow*QS_STR + acol) * 4;
    uint32_t ps_addr = sb + (PS_OFF + arow*PS_STR + acol) * 4;

    // row identities for this thread
    int lrow0 = 16*wm + lr;         // local row of c0/c1
    int qg0 = q0 + lrow0;
    int qg1 = qg0 + 8;

    float m0v = -1e30f, m1v = -1e30f, l0v = 0.f, l1v = 0.f;
    float O[16][4];
#pragma unroll
    for (int i = 0; i < 16; i++)
#pragma unroll
        for (int j = 0; j < 4; j++) O[i][j] = 0.f;

    float* Red = smf + RED_OFF;
    float* Sum = smf + SUM_OFF;

    for (int t = 0; t < nt; t++) {
        int kt = kt0 + t * ABK;
        int s  = t & 1;
        CP_WAIT_ALL();
        __syncthreads();                       // tile data ready; prev tile fully done
        if (t + 1 < nt) { issueKV(kt0 + (t+1)*ABK, s ^ 1); CP_COMMIT(); }

        // ---- S = Q K^T ----
        float sacc[2][4];
#pragma unroll
        for (int nb = 0; nb < 2; nb++)
#pragma unroll
            for (int j = 0; j < 4; j++) sacc[nb][j] = 0.f;

        const float* kb0 = smf + KS_OFF + s*KS_STG + (16*wn + lr)*KS_STR + lc;
#pragma unroll 8
        for (int k8 = 0; k8 < 32; k8++) {
            uint32_t a0, a1, a2, a3;
            ldsm_x4(a0, a1, a2, a3, qs_addr + k8*32);
#pragma unroll
            for (int nb = 0; nb < 2; nb++) {
                const float* kb = kb0 + nb*8*KS_STR + k8*8;
                uint32_t b0 = __float_as_uint(kb[0]);
                uint32_t b1 = __float_as_uint(kb[4]);
                mma_tf32(sacc[nb], a0, a1, a2, a3, b0, b1);
            }
        }

        // ---- masked scale + online softmax ----
        float sv[2][4];
        float mx0 = -1e30f, mx1 = -1e30f;
#pragma unroll
        for (int nb = 0; nb < 2; nb++) {
#pragma unroll
            for (int j = 0; j < 4; j++) {
                int kg = kt + 16*wn + nb*8 + 2*lc + (j & 1);
                int qg = (j < 2) ? qg0 : qg1;
                float v = sacc[nb][j] * SM_SCALE;
                bool valid = (kg <= qg) && (qg - kg < WINDOW);
                v = valid ? v : -1e30f;
                sv[nb][j] = v;
                if (j < 2) mx0 = fmaxf(mx0, v); else mx1 = fmaxf(mx1, v);
            }
        }
        mx0 = fmaxf(mx0, __shfl_xor_sync(0xffffffffu, mx0, 1));
        mx0 = fmaxf(mx0, __shfl_xor_sync(0xffffffffu, mx0, 2));
        mx1 = fmaxf(mx1, __shfl_xor_sync(0xffffffffu, mx1, 1));
        mx1 = fmaxf(mx1, __shfl_xor_sync(0xffffffffu, mx1, 2));
        if (lc == 0) {
            Red[wn*64 + lrow0]     = mx0;
            Red[wn*64 + lrow0 + 8] = mx1;
        }
        __syncthreads();
        float mt0 = fmaxf(Red[lrow0],     Red[64 + lrow0]);
        float mt1 = fmaxf(Red[lrow0 + 8], Red[64 + lrow0 + 8]);
        float mn0 = fmaxf(m0v, mt0);
        float mn1 = fmaxf(m1v, mt1);
        float al0 = __expf(m0v - mn0);
        float al1 = __expf(m1v - mn1);

        float s0 = 0.f, s1 = 0.f;
        float pv[2][4];
#pragma unroll
        for (int nb = 0; nb < 2; nb++) {
#pragma unroll
            for (int j = 0; j < 4; j++) {
                float mn = (j < 2) ? mn0 : mn1;
                float p = (sv[nb][j] > -1e29f) ? __expf(sv[nb][j] - mn) : 0.f;
                pv[nb][j] = cvt_tf32(p);
                if (j < 2) s0 += p; else s1 += p;
            }
        }
        s0 += __shfl_xor_sync(0xffffffffu, s0, 1);
        s0 += __shfl_xor_sync(0xffffffffu, s0, 2);
        s1 += __shfl_xor_sync(0xffffffffu, s1, 1);
        s1 += __shfl_xor_sync(0xffffffffu, s1, 2);
        if (lc == 0) {
            Sum[wn*64 + lrow0]     = s0;
            Sum[wn*64 + lrow0 + 8] = s1;
        }
        // write P tiles
#pragma unroll
        for (int nb = 0; nb < 2; nb++) {
            int col = 16*wn + nb*8 + 2*lc;
            *(float2*)(smf + PS_OFF + lrow0*PS_STR + col)       = make_float2(pv[nb][0], pv[nb][1]);
            *(float2*)(smf + PS_OFF + (lrow0 + 8)*PS_STR + col) = make_float2(pv[nb][2], pv[nb][3]);
        }
        __syncthreads();
        l0v = l0v * al0 + Sum[lrow0]     + Sum[64 + lrow0];
        l1v = l1v * al1 + Sum[lrow0 + 8] + Sum[64 + lrow0 + 8];
        m0v = mn0; m1v = mn1;
#pragma unroll
        for (int i = 0; i < 16; i++) {
            O[i][0] *= al0; O[i][1] *= al0;
            O[i][2] *= al1; O[i][3] *= al1;
        }

        // ---- O += P V ----
        const float* vb0 = smf + VS_OFF + s*VS_STG + lc*VS_STR + 128*wn + lr;
#pragma unroll
        for (int k8 = 0; k8 < 4; k8++) {
            uint32_t p0, p1, p2, p3;
            ldsm_x4(p0, p1, p2, p3, ps_addr + k8*32);
            const float* vb = vb0 + k8*8*VS_STR;
#pragma unroll
            for (int nb = 0; nb < 16; nb++) {
                uint32_t b0 = __float_as_uint(vb[nb*8]);
                uint32_t b1 = __float_as_uint(vb[4*VS_STR + nb*8]);
                mma_tf32(O[nb], p0, p1, p2, p3, b0, b1);
            }
        }
    }

    // ---- epilogue ----
    float inv0 = 1.f / l0v, inv1 = 1.f / l1v;
    float* out0 = g_att + (size_t)(b*Tseq + qg0) * ATTN_N + h * Dh + 128*wn + 2*lc;
    float* out1 = g_att + (size_t)(b*Tseq + qg1) * ATTN_N + h * Dh + 128*wn + 2*lc;
#pragma unroll
    for (int nb = 0; nb < 16; nb++) {
        *(float2*)(out0 + nb*8) = make_float2(O[nb][0]*inv0, O[nb][1]*inv0);
        *(float2*)(out1 + nb*8) = make_float2(O[nb][2]*inv1, O[nb][3]*inv1);
    }
}

// ---------------- launch ------------------------------------------------------------
extern "C" void kernel_launch(void* const* d_in, const int* in_sizes, int n_in,
                              void* d_out, int out_size) {
    const float* x   = (const float*)d_in[0];
    const float* Wq  = (const float*)d_in[1];
    const float* Wk  = (const float*)d_in[2];
    const float* Wv  = (const float*)d_in[3];
    const float* Wo  = (const float*)d_in[4];
    const float* qsc = (const float*)d_in[5];
    const float* ksc = (const float*)d_in[6];
    const int*   seg = (const int*)d_in[7];
    float* out = (float*)d_out;

    const int* cur;
    if (n_in > 9) cur = (const int*)d_in[9];
    else {
        void* zp; cudaGetSymbolAddress(&zp, g_zero_int);
        cur = (const int*)zp;
    }

    float *qkv, *att;
    cudaGetSymbolAddress((void**)&qkv, g_qkv);
    cudaGetSymbolAddress((void**)&att, g_att);
    float *xfh, *xfl, *afh, *afl;
    cudaGetSymbolAddress((void**)&xfh, g_xf_hi); cudaGetSymbolAddress((void**)&xfl, g_xf_lo);
    cudaGetSymbolAddress((void**)&afh, g_af_hi); cudaGetSymbolAddress((void**)&afl, g_af_lo);
    float *wqh, *wql, *wkh, *wkl, *wvh, *wvl, *woh, *wol;
    cudaGetSymbolAddress((void**)&wqh, g_wq_hi); cudaGetSymbolAddress((void**)&wql, g_wq_lo);
    cudaGetSymbolAddress((void**)&wkh, g_wk_hi); cudaGetSymbolAddress((void**)&wkl, g_wk_lo);
    cudaGetSymbolAddress((void**)&wvh, g_wv_hi); cudaGetSymbolAddress((void**)&wvl, g_wv_lo);
    cudaGetSymbolAddress((void**)&woh, g_wo_hi); cudaGetSymbolAddress((void**)&wol, g_wo_lo);

    cudaFuncSetAttribute(gemm_mma_kernel, cudaFuncAttributeMaxDynamicSharedMemorySize, GEMM_SMEM);
    cudaFuncSetAttribute(attn_mma_kernel, cudaFuncAttributeMaxDynamicSharedMemorySize, ATTN_SMEM);

    seg_first_kernel<<<Bsz, 256>>>(seg);
    rope_table_kernel<<<ROWS, 128>>>(seg, cur);

    pack_a_kernel<<<dim3(ROWS/16, Hdim/64), 256>>>(x, Hdim, xfh, xfl);
    pack_w_kernel<<<dim3(2560/128, 2048/8), 256>>>(Wq, 2560, 2048, wqh, wql);
    pack_w_kernel<<<dim3(2560/128, 1024/8), 256>>>(Wk, 2560, 1024, wkh, wkl);
    pack_w_kernel<<<dim3(2560/128, 1024/8), 256>>>(Wv, 2560, 1024, wvh, wvl);
    pack_w_kernel<<<dim3(2048/128, 2560/8), 256>>>(Wo, 2048, 2560, woh, wol);

    gemm_mma_kernel<<<dim3(2048/128, ROWS/128), 256, GEMM_SMEM>>>(xfh, xfl, wqh, wql, qkv,        QKVN, Hdim);
    gemm_mma_kernel<<<dim3(1024/128, ROWS/128), 256, GEMM_SMEM>>>(xfh, xfl, wkh, wkl, qkv + 2048, QKVN, Hdim);
    gemm_mma_kernel<<<dim3(1024/128, ROWS/128), 256, GEMM_SMEM>>>(xfh, xfl, wvh, wvl, qkv + 3072, QKVN, Hdim);

    rmsnorm_rope_kernel<<<ROWS * 16, 256>>>(qsc, ksc);

    attn_mma_kernel<<<dim3(Tseq/64, NH, Bsz), 256, ATTN_SMEM>>>();

    pack_a_kernel<<<dim3(ROWS/16, ATTN_N/64), 256>>>(att, ATTN_N, afh, afl);
    gemm_mma_kernel<<<dim3(Hdim/128, ROWS/128), 256, GEMM_SMEM>>>(afh, afl, woh, wol, out, Hdim, ATTN_N);
}

// round 6
// speedup vs baseline: 3.5744x; 1.6557x over previous
#include <cuda_runtime.h>
#include <cuda_bf16.h>
#include <math.h>
#include <stdint.h>

#define Bsz    2
#define Tseq   2048
#define Hdim   2560
#define NH     8
#define NKV    4
#define Dh     256
#define WINDOW 1024
#define QKVN   4096          // 2048 q | 1024 k | 1024 v
#define ROWS   (Bsz*Tseq)    // 4096
#define ATTN_N (NH*Dh)       // 2048

// ---------------- scratch (device globals) -----------------------------------
__device__ float g_qkv[(size_t)ROWS * QKVN];   // 64 MB
__device__ float g_sin[(size_t)ROWS * (Dh/2)];
__device__ float g_cos[(size_t)ROWS * (Dh/2)];
__device__ int   g_first[Bsz];
__device__ int   g_zero_int = 0;

// fragment-major bf16 hi/lo planes (uint32 = bf16x2)
__device__ uint32_t g_xf_hi[(size_t)ROWS * Hdim / 2];
__device__ uint32_t g_xf_lo[(size_t)ROWS * Hdim / 2];
__device__ uint32_t g_af_hi[(size_t)ROWS * ATTN_N / 2];   // attn out, frag-major
__device__ uint32_t g_af_lo[(size_t)ROWS * ATTN_N / 2];
__device__ uint32_t g_wq_hi[(size_t)2048 * 2560 / 2];
__device__ uint32_t g_wq_lo[(size_t)2048 * 2560 / 2];
__device__ uint32_t g_wk_hi[(size_t)1024 * 2560 / 2];
__device__ uint32_t g_wk_lo[(size_t)1024 * 2560 / 2];
__device__ uint32_t g_wv_hi[(size_t)1024 * 2560 / 2];
__device__ uint32_t g_wv_lo[(size_t)1024 * 2560 / 2];
__device__ uint32_t g_wo_hi[(size_t)2560 * 2048 / 2];
__device__ uint32_t g_wo_lo[(size_t)2560 * 2048 / 2];

// ---------------- helpers ------------------------------------------------------
__device__ __forceinline__ uint32_t smem_u32(const void* p) {
    uint32_t a;
    asm("{ .reg .u64 t; cvta.to.shared.u64 t, %1; cvt.u32.u64 %0, t; }"
        : "=r"(a) : "l"(p));
    return a;
}
__device__ __forceinline__ float cvt_tf32(float x) {
    float r; asm("cvt.rna.tf32.f32 %0, %1;" : "=f"(r) : "f"(x)); return r;
}
// pack two floats to bf16x2 (x -> low half, y -> high half)
__device__ __forceinline__ uint32_t bf2(float x, float y) {
    uint32_t r;
    asm("cvt.rn.bf16x2.f32 %0, %1, %2;" : "=r"(r) : "f"(y), "f"(x));
    return r;
}
// bf16 hi/lo split of a float pair
__device__ __forceinline__ void split2(float x, float y, uint32_t& hi, uint32_t& lo) {
    float xh = __bfloat162float(__float2bfloat16_rn(x));
    float yh = __bfloat162float(__float2bfloat16_rn(y));
    hi = bf2(xh, yh);
    lo = bf2(x - xh, y - yh);
}
__device__ __forceinline__ void mma_bf16(float* c,
    uint32_t a0, uint32_t a1, uint32_t a2, uint32_t a3,
    uint32_t b0, uint32_t b1)
{
    asm volatile(
        "mma.sync.aligned.m16n8k16.row.col.f32.bf16.bf16.f32 "
        "{%0,%1,%2,%3}, {%4,%5,%6,%7}, {%8,%9}, {%0,%1,%2,%3};"
        : "+f"(c[0]), "+f"(c[1]), "+f"(c[2]), "+f"(c[3])
        : "r"(a0), "r"(a1), "r"(a2), "r"(a3), "r"(b0), "r"(b1));
}
__device__ __forceinline__ void mma_tf32(float* c,
    uint32_t a0, uint32_t a1, uint32_t a2, uint32_t a3,
    uint32_t b0, uint32_t b1)
{
    asm volatile(
        "mma.sync.aligned.m16n8k8.row.col.f32.tf32.tf32.f32 "
        "{%0,%1,%2,%3}, {%4,%5,%6,%7}, {%8,%9}, {%0,%1,%2,%3};"
        : "+f"(c[0]), "+f"(c[1]), "+f"(c[2]), "+f"(c[3])
        : "r"(a0), "r"(a1), "r"(a2), "r"(a3), "r"(b0), "r"(b1));
}
__device__ __forceinline__ void ldsm_x4(uint32_t& r0, uint32_t& r1,
                                        uint32_t& r2, uint32_t& r3, uint32_t addr)
{
    asm volatile("ldmatrix.sync.aligned.m8n8.x4.shared.b16 {%0,%1,%2,%3}, [%4];"
        : "=r"(r0), "=r"(r1), "=r"(r2), "=r"(r3) : "r"(addr));
}
#define CP_ASYNC16(dst, src) \
    asm volatile("cp.async.cg.shared.global [%0], [%1], 16;" :: "r"(dst), "l"(src))
#define CP_COMMIT()   asm volatile("cp.async.commit_group;" ::: "memory")
#define CP_WAIT1()    asm volatile("cp.async.wait_group 1;" ::: "memory")
#define CP_WAIT_ALL() asm volatile("cp.async.wait_group 0;" ::: "memory")

// ---------------- pos helper ----------------------------------------------------
__global__ void seg_first_kernel(const int* __restrict__ seg) {
    __shared__ int smax;
    __shared__ int sidx;
    int b = blockIdx.x, tid = threadIdx.x;
    if (tid == 0) { smax = -2147483647; sidx = 2147483647; }
    __syncthreads();
    int mx = -2147483647;
    for (int t = tid; t < Tseq; t += blockDim.x) mx = max(mx, seg[b*Tseq + t]);
    atomicMax(&smax, mx);
    __syncthreads();
    int mv = smax;
    int mi = 2147483647;
    for (int t = tid; t < Tseq; t += blockDim.x)
        if (seg[b*Tseq + t] == mv) mi = min(mi, t);
    atomicMin(&sidx, mi);
    __syncthreads();
    if (tid == 0) g_first[b] = sidx;
}

// ---------------- rope sin/cos tables --------------------------------------------
__global__ void rope_table_kernel(const int* __restrict__ seg,
                                  const int* __restrict__ cur_ind) {
    int row = blockIdx.x;
    int k   = threadIdx.x;
    int b = row / Tseq, t = row % Tseq;
    int sv = seg[row];
    long long pos = (sv != 0) ? (long long)(t - g_first[b]) : (1ll << 30);
    pos += (long long)cur_ind[0];
    float posf = (float)pos;
    float freq = powf(10000.0f, -((float)(2*k)) / (float)Dh);
    float ang  = posf * freq;
    g_sin[(size_t)row*128 + k] = sinf(ang);
    g_cos[(size_t)row*128 + k] = cosf(ang);
}

// ---------------- pack A (row-major [M][K] float -> frag-major bf16 hi/lo) --------
// A-frag (m16n8k16): per 16-row block per k16: 128 u32, addr = lane*4 + reg
// reg0=(lr,2lc|2lc+1) reg1=(lr+8,..) reg2=(lr,2lc+8|9) reg3=(lr+8,2lc+8|9)
__global__ void __launch_bounds__(256) pack_a_kernel(
    const float* __restrict__ A, int K,
    uint32_t* __restrict__ Fhi, uint32_t* __restrict__ Flo)
{
    __shared__ float tile[16][68];
    int r0 = blockIdx.x * 16, k0 = blockIdx.y * 64;
    int tid = threadIdx.x;
    {
        int row = tid >> 4, q = tid & 15;
        float4 v = *(const float4*)(A + (size_t)(r0 + row) * K + k0 + q*4);
        *(float4*)&tile[row][q*4] = v;
    }
    __syncthreads();
    int k16l = tid >> 6;              // 0..3
    int r6   = tid & 63;
    int rpair = (r6 >> 5) * 2;        // 0 or 2
    int lane  = r6 & 31;
    int lr = lane >> 2, lc = lane & 3;
    int cb = k16l*16 + 2*lc + (rpair ? 8 : 0);
    float v00 = tile[lr    ][cb], v01 = tile[lr    ][cb+1];
    float v10 = tile[lr + 8][cb], v11 = tile[lr + 8][cb+1];
    uint32_t h0, l0, h1, l1;
    split2(v00, v01, h0, l0);
    split2(v10, v11, h1, l1);
    int K16 = K >> 4;
    size_t off = ((size_t)blockIdx.x * K16 + blockIdx.y*4 + k16l) * 128 + lane*4 + rpair;
    Fhi[off]   = h0;  Flo[off]   = l0;
    Fhi[off+1] = h1;  Flo[off+1] = l1;
}

// ---------------- pack W ([K][N] float -> B frag-major bf16 hi/lo) ----------------
// B-frag (k16xn8): per 8-col block per k16: 64 u32, addr = lane*2 + reg
// b0=(k=2lc|2lc+1, n=lr) b1=(k=2lc+8|9, n=lr)
__global__ void __launch_bounds__(256) pack_w_kernel(
    const float* __restrict__ W, int K, int N,
    uint32_t* __restrict__ Fhi, uint32_t* __restrict__ Flo)
{
    __shared__ float tile[128][9];
    int k0 = blockIdx.x * 128, n0 = blockIdx.y * 8;
    int tid = threadIdx.x;
    {
        int kl = tid >> 1, half = tid & 1;
        float4 v = *(const float4*)(W + (size_t)(k0 + kl) * N + n0 + half*4);
        tile[kl][half*4 + 0] = v.x;
        tile[kl][half*4 + 1] = v.y;
        tile[kl][half*4 + 2] = v.z;
        tile[kl][half*4 + 3] = v.w;
    }
    __syncthreads();
    int k16l = tid >> 5, lane = tid & 31;
    int lr = lane >> 2, lc = lane & 3;
    int kb = k16l * 16;
    float v0 = tile[kb + 2*lc    ][lr];
    float v1 = tile[kb + 2*lc + 1][lr];
    float v2 = tile[kb + 2*lc + 8][lr];
    float v3 = tile[kb + 2*lc + 9][lr];
    uint32_t h0, l0, h1, l1;
    split2(v0, v1, h0, l0);
    split2(v2, v3, h1, l1);
    int K16 = K >> 4;
    size_t off = ((size_t)blockIdx.y * K16 + blockIdx.x*8 + k16l) * 64 + lane*2;
    Fhi[off]   = h0;  Flo[off]   = l0;
    Fhi[off+1] = h1;  Flo[off+1] = l1;
}

// ---------------- frag-major split-bf16 GEMM --------------------------------------
// CTA 128x128, 8 warps (2M x 4N), warp 64x32, K chunk = 64 (4 k16 steps).
// Stage (u32): [Ahi 4096][Alo 4096][Bhi 4096][Blo 4096] = 64KB. 3 stages.
#define STG_U32 16384
#define NSTG    3
#define GEMM_SMEM (NSTG * STG_U32 * 4)

__global__ void __launch_bounds__(256, 1) gemm_mma_kernel(
    const uint32_t* __restrict__ Ahi, const uint32_t* __restrict__ Alo,
    const uint32_t* __restrict__ Bhi, const uint32_t* __restrict__ Blo,
    float* __restrict__ C, int ldc, int K)
{
    extern __shared__ uint32_t smu[];
    int tid  = threadIdx.x;
    int lane = tid & 31, wid = tid >> 5;
    int wm = wid >> 2, wn = wid & 3;
    int m0 = blockIdx.y * 128, n0 = blockIdx.x * 128;
    int K16 = K >> 4;
    int rb0 = m0 >> 4, nb0 = n0 >> 3;
    const int nc = K >> 6;

    float acc[4][4][4];
#pragma unroll
    for (int i = 0; i < 4; i++)
#pragma unroll
        for (int j = 0; j < 4; j++)
#pragma unroll
            for (int r = 0; r < 4; r++) acc[i][j][r] = 0.f;

    uint32_t sbase = smem_u32(smu);

    auto issue = [&](int c, int s) {
        uint32_t sd = sbase + s * (STG_U32 * 4);
        int c4 = c * 4;
#pragma unroll
        for (int i = 0; i < 16; i++) {
            int idx = tid + i * 256;          // 16B unit index, 0..4095
            int plane = idx >> 10, sub = idx & 1023;
            const uint32_t* src;
            if (plane < 2) {
                int rb = sub >> 7, k16 = (sub >> 5) & 3, j = sub & 31;
                const uint32_t* pl = plane ? Alo : Ahi;
                src = pl + ((size_t)(rb0 + rb) * K16 + c4 + k16) * 128 + j*4;
            } else {
                int nb = sub >> 6, k16 = (sub >> 4) & 3, j = sub & 15;
                const uint32_t* pl = (plane == 3) ? Blo : Bhi;
                src = pl + ((size_t)(nb0 + nb) * K16 + c4 + k16) * 64 + j*4;
            }
            CP_ASYNC16(sd + idx * 16, src);
        }
    };

    issue(0, 0); CP_COMMIT();
    if (nc > 1) issue(1, 1);
    CP_COMMIT();

    for (int c = 0; c < nc; c++) {
        CP_WAIT1();
        __syncthreads();

        const uint32_t* sA = smu + (c % NSTG) * STG_U32;
        const uint32_t* pA = sA + (wm * 4) * 512 + lane * 4;
        const uint32_t* pB = sA + 8192 + (wn * 4) * 256 + lane * 2;

#pragma unroll
        for (int k16 = 0; k16 < 4; k16++) {
            uint4 AH[4], AL[4];
            uint2 BH[4], BL[4];
#pragma unroll
            for (int mt = 0; mt < 4; mt++) {
                AH[mt] = *(const uint4*)(pA + mt*512 + k16*128);
                AL[mt] = *(const uint4*)(pA + 4096 + mt*512 + k16*128);
            }
#pragma unroll
            for (int nt = 0; nt < 4; nt++) {
                BH[nt] = *(const uint2*)(pB + nt*256 + k16*64);
                BL[nt] = *(const uint2*)(pB + 4096 + nt*256 + k16*64);
            }
#pragma unroll
            for (int mt = 0; mt < 4; mt++)
#pragma unroll
                for (int nt = 0; nt < 4; nt++) {
                    float* cc = acc[mt][nt];
                    mma_bf16(cc, AH[mt].x, AH[mt].y, AH[mt].z, AH[mt].w,
                             BH[nt].x, BH[nt].y);
                    mma_bf16(cc, AL[mt].x, AL[mt].y, AL[mt].z, AL[mt].w,
                             BH[nt].x, BH[nt].y);
                    mma_bf16(cc, AH[mt].x, AH[mt].y, AH[mt].z, AH[mt].w,
                             BL[nt].x, BL[nt].y);
                }
        }

        if (c + 2 < nc) issue(c + 2, (c + 2) % NSTG);
        CP_COMMIT();
    }

#pragma unroll
    for (int mt = 0; mt < 4; mt++) {
        int row0 = m0 + wm*64 + mt*16 + (lane >> 2);
#pragma unroll
        for (int nt = 0; nt < 4; nt++) {
            int col = n0 + wn*32 + nt*8 + 2*(lane & 3);
            float* cc = acc[mt][nt];
            *(float2*)(C + (size_t)row0 * ldc + col)       = make_float2(cc[0], cc[1]);
            *(float2*)(C + (size_t)(row0 + 8) * ldc + col) = make_float2(cc[2], cc[3]);
        }
    }
}

// ---------------- RMSNorm + RoPE (q,k) + tf32 rounding (q,k,v) --------------------
__global__ void __launch_bounds__(256) rmsnorm_rope_kernel(
    const float* __restrict__ qsc, const float* __restrict__ ksc)
{
    int bid = blockIdx.x;
    int row = bid >> 4;
    int hi  = bid & 15;
    int tid = threadIdx.x;
    if (hi >= 12) {
        float* p = g_qkv + (size_t)row * QKVN + NH*Dh + NKV*Dh + (hi-12) * Dh;
        p[tid] = cvt_tf32(p[tid]);
        return;
    }
    int off; const float* sc;
    if (hi < NH) { off = hi * Dh;              sc = qsc; }
    else         { off = NH*Dh + (hi-NH) * Dh; sc = ksc; }
    float* p = g_qkv + (size_t)row * QKVN + off;
    float x = p[tid];
    float ss = x * x;
#pragma unroll
    for (int o = 16; o; o >>= 1) ss += __shfl_xor_sync(0xffffffffu, ss, o);
    __shared__ float red[8];
    __shared__ float tot;
    __shared__ float sy[256];
    if ((tid & 31) == 0) red[tid >> 5] = ss;
    __syncthreads();
    if (tid == 0) {
        float t = 0.f;
        for (int i = 0; i < 8; i++) t += red[i];
        tot = t;
    }
    __syncthreads();
    float rms = rsqrtf(tot * (1.0f / Dh) + 1e-6f);
    float y = x * rms * (1.0f + sc[tid]);
    sy[tid] = y;
    __syncthreads();
    int kidx = tid & 127;
    float s_ = g_sin[(size_t)row*128 + kidx];
    float c_ = g_cos[(size_t)row*128 + kidx];
    float out;
    if (tid < 128) out = y * c_ - sy[tid + 128] * s_;
    else           out = y * c_ + sy[tid - 128] * s_;
    p[tid] = cvt_tf32(out);
}

// ---------------- tensor-core flash attention (tf32) ------------------------------
// Epilogue writes frag-major bf16 hi/lo directly (A operand of the Wo GEMM).
#define ABK       32
#define QS_STR    260
#define KS_STR    260
#define VS_STR    264
#define PS_STR    36
#define QS_OFF    0
#define KS_OFF    16640
#define KS_STG    8320
#define VS_OFF    (KS_OFF + 2*KS_STG)
#define VS_STG    8448
#define PS_OFF    (VS_OFF + 2*VS_STG)
#define RED_OFF   (PS_OFF + 64*PS_STR)
#define SUM_OFF   (RED_OFF + 128)
#define ATTN_SMEM ((SUM_OFF + 128) * 4)
#define SM_SCALE  0.0625f

__global__ void __launch_bounds__(256, 1) attn_mma_kernel(
    uint32_t* __restrict__ AFhi, uint32_t* __restrict__ AFlo)
{
    extern __shared__ float smf[];
    uint32_t sb = smem_u32(smf);
    int tid  = threadIdx.x;
    int lane = tid & 31, wid = tid >> 5;
    int lr = lane >> 2, lc = lane & 3;
    int wm = wid >> 1, wn = wid & 1;

    int q0 = blockIdx.x * 64;
    int h  = blockIdx.y, b = blockIdx.z;
    int kvh = h >> 1;
    const float* baseq = g_qkv + (size_t)b * Tseq * QKVN + h * Dh;
    const float* basek = g_qkv + (size_t)b * Tseq * QKVN + NH*Dh + kvh * Dh;
    const float* basev = g_qkv + (size_t)b * Tseq * QKVN + NH*Dh + NKV*Dh + kvh * Dh;

    auto issueQ = [&]() {
#pragma unroll
        for (int i = 0; i < 16; i++) {
            int idx = tid + i * 256;
            int r = idx >> 6, c = idx & 63;
            CP_ASYNC16(sb + (QS_OFF + r*QS_STR + c*4) * 4,
                       baseq + (size_t)(q0 + r) * QKVN + c*4);
        }
    };
    auto issueKV = [&](int kt, int s) {
#pragma unroll
        for (int i = 0; i < 8; i++) {
            int idx = tid + i * 256;
            int r = idx >> 6, c = idx & 63;
            CP_ASYNC16(sb + (KS_OFF + s*KS_STG + r*KS_STR + c*4) * 4,
                       basek + (size_t)(kt + r) * QKVN + c*4);
        }
#pragma unroll
        for (int i = 0; i < 8; i++) {
            int idx = tid + i * 256;
            int r = idx >> 6, c = idx & 63;
            CP_ASYNC16(sb + (VS_OFF + s*VS_STG + r*VS_STR + c*4) * 4,
                       basev + (size_t)(kt + r) * QKVN + c*4);
        }
    };

    int kstart = q0 - (WINDOW - 1); if (kstart < 0) kstart = 0;
    int kt0 = kstart & ~(ABK - 1);
    int nt  = (q0 + 64 - kt0) >> 5;

    issueQ();
    issueKV(kt0, 0);
    CP_COMMIT();

    int arow = 16*wm + (lane & 7) + ((lane >> 3) & 1) * 8;
    int acol = (lane >> 4) * 4;
    uint32_t qs_addr = sb + (QS_OFF + arow*QS_STR + acol) * 4;
    uint32_t ps_addr = sb + (PS_OFF + arow*PS_STR + acol) * 4;

    int lrow0 = 16*wm + lr;
    int qg0 = q0 + lrow0;

    float m0v = -1e30f, m1v = -1e30f, l0v = 0.f, l1v = 0.f;
    float O[16][4];
#pragma unroll
    for (int i = 0; i < 16; i++)
#pragma unroll
        for (int j = 0; j < 4; j++) O[i][j] = 0.f;

    float* Red = smf + RED_OFF;
    float* Sum = smf + SUM_OFF;

    for (int t = 0; t < nt; t++) {
        int kt = kt0 + t * ABK;
        int s  = t & 1;
        CP_WAIT_ALL();
        __syncthreads();
        if (t + 1 < nt) { issueKV(kt0 + (t+1)*ABK, s ^ 1); CP_COMMIT(); }

        float sacc[2][4];
#pragma unroll
        for (int nb = 0; nb < 2; nb++)
#pragma unroll
            for (int j = 0; j < 4; j++) sacc[nb][j] = 0.f;

        const float* kb0 = smf + KS_OFF + s*KS_STG + (16*wn + lr)*KS_STR + lc;
#pragma unroll 8
        for (int k8 = 0; k8 < 32; k8++) {
            uint32_t a0, a1, a2, a3;
            ldsm_x4(a0, a1, a2, a3, qs_addr + k8*32);
#pragma unroll
            for (int nb = 0; nb < 2; nb++) {
                const float* kb = kb0 + nb*8*KS_STR + k8*8;
                uint32_t b0 = __float_as_uint(kb[0]);
                uint32_t b1 = __float_as_uint(kb[4]);
                mma_tf32(sacc[nb], a0, a1, a2, a3, b0, b1);
            }
        }

        float sv[2][4];
        float mx0 = -1e30f, mx1 = -1e30f;
#pragma unroll
        for (int nb = 0; nb < 2; nb++) {
#pragma unroll
            for (int j = 0; j < 4; j++) {
                int kg = kt + 16*wn + nb*8 + 2*lc + (j & 1);
                int qg = (j < 2) ? qg0 : (qg0 + 8);
                float v = sacc[nb][j] * SM_SCALE;
                bool valid = (kg <= qg) && (qg - kg < WINDOW);
                v = valid ? v : -1e30f;
                sv[nb][j] = v;
                if (j < 2) mx0 = fmaxf(mx0, v); else mx1 = fmaxf(mx1, v);
            }
        }
        mx0 = fmaxf(mx0, __shfl_xor_sync(0xffffffffu, mx0, 1));
        mx0 = fmaxf(mx0, __shfl_xor_sync(0xffffffffu, mx0, 2));
        mx1 = fmaxf(mx1, __shfl_xor_sync(0xffffffffu, mx1, 1));
        mx1 = fmaxf(mx1, __shfl_xor_sync(0xffffffffu, mx1, 2));
        if (lc == 0) {
            Red[wn*64 + lrow0]     = mx0;
            Red[wn*64 + lrow0 + 8] = mx1;
        }
        __syncthreads();
        float mt0 = fmaxf(Red[lrow0],     Red[64 + lrow0]);
        float mt1 = fmaxf(Red[lrow0 + 8], Red[64 + lrow0 + 8]);
        float mn0 = fmaxf(m0v, mt0);
        float mn1 = fmaxf(m1v, mt1);
        float al0 = __expf(m0v - mn0);
        float al1 = __expf(m1v - mn1);

        float s0 = 0.f, s1 = 0.f;
        float pv[2][4];
#pragma unroll
        for (int nb = 0; nb < 2; nb++) {
#pragma unroll
            for (int j = 0; j < 4; j++) {
                float mn = (j < 2) ? mn0 : mn1;
                float p = (sv[nb][j] > -1e29f) ? __expf(sv[nb][j] - mn) : 0.f;
                pv[nb][j] = cvt_tf32(p);
                if (j < 2) s0 += p; else s1 += p;
            }
        }
        s0 += __shfl_xor_sync(0xffffffffu, s0, 1);
        s0 += __shfl_xor_sync(0xffffffffu, s0, 2);
        s1 += __shfl_xor_sync(0xffffffffu, s1, 1);
        s1 += __shfl_xor_sync(0xffffffffu, s1, 2);
        if (lc == 0) {
            Sum[wn*64 + lrow0]     = s0;
            Sum[wn*64 + lrow0 + 8] = s1;
        }
#pragma unroll
        for (int nb = 0; nb < 2; nb++) {
            int col = 16*wn + nb*8 + 2*lc;
            *(float2*)(smf + PS_OFF + lrow0*PS_STR + col)       = make_float2(pv[nb][0], pv[nb][1]);
            *(float2*)(smf + PS_OFF + (lrow0 + 8)*PS_STR + col) = make_float2(pv[nb][2], pv[nb][3]);
        }
        __syncthreads();
        l0v = l0v * al0 + Sum[lrow0]     + Sum[64 + lrow0];
        l1v = l1v * al1 + Sum[lrow0 + 8] + Sum[64 + lrow0 + 8];
        m0v = mn0; m1v = mn1;
#pragma unroll
        for (int i = 0; i < 16; i++) {
            O[i][0] *= al0; O[i][1] *= al0;
            O[i][2] *= al1; O[i][3] *= al1;
        }

        const float* vb0 = smf + VS_OFF + s*VS_STG + lc*VS_STR + 128*wn + lr;
#pragma unroll
        for (int k8 = 0; k8 < 4; k8++) {
            uint32_t p0, p1, p2, p3;
            ldsm_x4(p0, p1, p2, p3, ps_addr + k8*32);
            const float* vb = vb0 + k8*8*VS_STR;
#pragma unroll
            for (int nb = 0; nb < 16; nb++) {
                uint32_t b0 = __float_as_uint(vb[nb*8]);
                uint32_t b1 = __float_as_uint(vb[4*VS_STR + nb*8]);
                mma_tf32(O[nb], p0, p1, p2, p3, b0, b1);
            }
        }
    }

    // ---- epilogue: write frag-major bf16 hi/lo (A of Wo GEMM) ----
    // global A row = b*Tseq + q; rowblock rb = (b*Tseq + q0)/16 + wm; K16 = 128.
    float inv0 = 1.f / l0v, inv1 = 1.f / l1v;
    int rb = ((b * Tseq + q0) >> 4) + wm;
#pragma unroll
    for (int nb = 0; nb < 16; nb++) {
        int k16 = h*16 + 8*wn + (nb >> 1);
        int reg = (nb & 1) * 2;
        size_t off = ((size_t)rb * 128 + k16) * 128 + lane*4 + reg;
        uint32_t h0, l0, h1, l1;
        split2(O[nb][0]*inv0, O[nb][1]*inv0, h0, l0);
        split2(O[nb][2]*inv1, O[nb][3]*inv1, h1, l1);
        AFhi[off]   = h0;  AFlo[off]   = l0;
        AFhi[off+1] = h1;  AFlo[off+1] = l1;
    }
}

// ---------------- launch ------------------------------------------------------------
extern "C" void kernel_launch(void* const* d_in, const int* in_sizes, int n_in,
                              void* d_out, int out_size) {
    const float* x   = (const float*)d_in[0];
    const float* Wq  = (const float*)d_in[1];
    const float* Wk  = (const float*)d_in[2];
    const float* Wv  = (const float*)d_in[3];
    const float* Wo  = (const float*)d_in[4];
    const float* qsc = (const float*)d_in[5];
    const float* ksc = (const float*)d_in[6];
    const int*   seg = (const int*)d_in[7];
    float* out = (float*)d_out;

    const int* cur;
    if (n_in > 9) cur = (const int*)d_in[9];
    else {
        void* zp; cudaGetSymbolAddress(&zp, g_zero_int);
        cur = (const int*)zp;
    }

    float* qkv;
    cudaGetSymbolAddress((void**)&qkv, g_qkv);
    uint32_t *xfh, *xfl, *afh, *afl;
    cudaGetSymbolAddress((void**)&xfh, g_xf_hi); cudaGetSymbolAddress((void**)&xfl, g_xf_lo);
    cudaGetSymbolAddress((void**)&afh, g_af_hi); cudaGetSymbolAddress((void**)&afl, g_af_lo);
    uint32_t *wqh, *wql, *wkh, *wkl, *wvh, *wvl, *woh, *wol;
    cudaGetSymbolAddress((void**)&wqh, g_wq_hi); cudaGetSymbolAddress((void**)&wql, g_wq_lo);
    cudaGetSymbolAddress((void**)&wkh, g_wk_hi); cudaGetSymbolAddress((void**)&wkl, g_wk_lo);
    cudaGetSymbolAddress((void**)&wvh, g_wv_hi); cudaGetSymbolAddress((void**)&wvl, g_wv_lo);
    cudaGetSymbolAddress((void**)&woh, g_wo_hi); cudaGetSymbolAddress((void**)&wol, g_wo_lo);

    cudaFuncSetAttribute(gemm_mma_kernel, cudaFuncAttributeMaxDynamicSharedMemorySize, GEMM_SMEM);
    cudaFuncSetAttribute(attn_mma_kernel, cudaFuncAttributeMaxDynamicSharedMemorySize, ATTN_SMEM);

    seg_first_kernel<<<Bsz, 256>>>(seg);
    rope_table_kernel<<<ROWS, 128>>>(seg, cur);

    pack_a_kernel<<<dim3(ROWS/16, Hdim/64), 256>>>(x, Hdim, xfh, xfl);
    pack_w_kernel<<<dim3(2560/128, 2048/8), 256>>>(Wq, 2560, 2048, wqh, wql);
    pack_w_kernel<<<dim3(2560/128, 1024/8), 256>>>(Wk, 2560, 1024, wkh, wkl);
    pack_w_kernel<<<dim3(2560/128, 1024/8), 256>>>(Wv, 2560, 1024, wvh, wvl);
    pack_w_kernel<<<dim3(2048/128, 2560/8), 256>>>(Wo, 2048, 2560, woh, wol);

    gemm_mma_kernel<<<dim3(2048/128, ROWS/128), 256, GEMM_SMEM>>>(xfh, xfl, wqh, wql, qkv,        QKVN, Hdim);
    gemm_mma_kernel<<<dim3(1024/128, ROWS/128), 256, GEMM_SMEM>>>(xfh, xfl, wkh, wkl, qkv + 2048, QKVN, Hdim);
    gemm_mma_kernel<<<dim3(1024/128, ROWS/128), 256, GEMM_SMEM>>>(xfh, xfl, wvh, wvl, qkv + 3072, QKVN, Hdim);

    rmsnorm_rope_kernel<<<ROWS * 16, 256>>>(qsc, ksc);

    attn_mma_kernel<<<dim3(Tseq/64, NH, Bsz), 256, ATTN_SMEM>>>(afh, afl);

    gemm_mma_kernel<<<dim3(Hdim/128, ROWS/128), 256, GEMM_SMEM>>>(afh, afl, woh, wol, out, Hdim, ATTN_N);
}

// round 7
// speedup vs baseline: 4.3505x; 1.2171x over previous
#include <cuda_runtime.h>
#include <cuda_bf16.h>
#include <cuda_fp16.h>
#include <math.h>
#include <stdint.h>

#define Bsz    2
#define Tseq   2048
#define Hdim   2560
#define NH     8
#define NKV    4
#define Dh     256
#define WINDOW 1024
#define QKVN   4096          // 2048 q | 1024 k | 1024 v
#define ROWS   (Bsz*Tseq)    // 4096
#define ATTN_N (NH*Dh)       // 2048

// ---------------- scratch (device globals) -----------------------------------
__device__ float g_qkv[(size_t)ROWS * QKVN];   // 64 MB
__device__ float g_sin[(size_t)ROWS * (Dh/2)];
__device__ float g_cos[(size_t)ROWS * (Dh/2)];
__device__ int   g_first[Bsz];
__device__ int   g_zero_int = 0;

// fragment-major fp16 hi/lo planes (uint32 = half2)
__device__ uint32_t g_xf_hi[(size_t)ROWS * Hdim / 2];
__device__ uint32_t g_xf_lo[(size_t)ROWS * Hdim / 2];
__device__ uint32_t g_af_hi[(size_t)ROWS * ATTN_N / 2];   // attn out, frag-major
__device__ uint32_t g_af_lo[(size_t)ROWS * ATTN_N / 2];
__device__ uint32_t g_wqkv_hi[(size_t)4096 * 2560 / 2];   // Wq|Wk|Wv concatenated (N-blocks)
__device__ uint32_t g_wqkv_lo[(size_t)4096 * 2560 / 2];
__device__ uint32_t g_wo_hi[(size_t)2560 * 2048 / 2];
__device__ uint32_t g_wo_lo[(size_t)2560 * 2048 / 2];

// ---------------- helpers ------------------------------------------------------
__device__ __forceinline__ uint32_t smem_u32(const void* p) {
    uint32_t a;
    asm("{ .reg .u64 t; cvta.to.shared.u64 t, %1; cvt.u32.u64 %0, t; }"
        : "=r"(a) : "l"(p));
    return a;
}
__device__ __forceinline__ float cvt_tf32(float x) {
    float r; asm("cvt.rna.tf32.f32 %0, %1;" : "=f"(r) : "f"(x)); return r;
}
__device__ __forceinline__ uint32_t h2pack(float x, float y) {
    __half2 h = __floats2half2_rn(x, y);
    return *(uint32_t*)&h;
}
// fp16 hi/lo split of a float pair
__device__ __forceinline__ void split2(float x, float y, uint32_t& hi, uint32_t& lo) {
    float xh = __half2float(__float2half_rn(x));
    float yh = __half2float(__float2half_rn(y));
    hi = h2pack(xh, yh);
    lo = h2pack(x - xh, y - yh);
}
__device__ __forceinline__ void mma_f16(float* c,
    uint32_t a0, uint32_t a1, uint32_t a2, uint32_t a3,
    uint32_t b0, uint32_t b1)
{
    asm volatile(
        "mma.sync.aligned.m16n8k16.row.col.f32.f16.f16.f32 "
        "{%0,%1,%2,%3}, {%4,%5,%6,%7}, {%8,%9}, {%0,%1,%2,%3};"
        : "+f"(c[0]), "+f"(c[1]), "+f"(c[2]), "+f"(c[3])
        : "r"(a0), "r"(a1), "r"(a2), "r"(a3), "r"(b0), "r"(b1));
}
__device__ __forceinline__ void mma_tf32(float* c,
    uint32_t a0, uint32_t a1, uint32_t a2, uint32_t a3,
    uint32_t b0, uint32_t b1)
{
    asm volatile(
        "mma.sync.aligned.m16n8k8.row.col.f32.tf32.tf32.f32 "
        "{%0,%1,%2,%3}, {%4,%5,%6,%7}, {%8,%9}, {%0,%1,%2,%3};"
        : "+f"(c[0]), "+f"(c[1]), "+f"(c[2]), "+f"(c[3])
        : "r"(a0), "r"(a1), "r"(a2), "r"(a3), "r"(b0), "r"(b1));
}
__device__ __forceinline__ void ldsm_x4(uint32_t& r0, uint32_t& r1,
                                        uint32_t& r2, uint32_t& r3, uint32_t addr)
{
    asm volatile("ldmatrix.sync.aligned.m8n8.x4.shared.b16 {%0,%1,%2,%3}, [%4];"
        : "=r"(r0), "=r"(r1), "=r"(r2), "=r"(r3) : "r"(addr));
}
#define CP_ASYNC16(dst, src) \
    asm volatile("cp.async.cg.shared.global [%0], [%1], 16;" :: "r"(dst), "l"(src))
#define CP_COMMIT()   asm volatile("cp.async.commit_group;" ::: "memory")
#define CP_WAIT1()    asm volatile("cp.async.wait_group 1;" ::: "memory")
#define CP_WAIT_ALL() asm volatile("cp.async.wait_group 0;" ::: "memory")

// ---------------- pos helper ----------------------------------------------------
__global__ void seg_first_kernel(const int* __restrict__ seg) {
    __shared__ int smax;
    __shared__ int sidx;
    int b = blockIdx.x, tid = threadIdx.x;
    if (tid == 0) { smax = -2147483647; sidx = 2147483647; }
    __syncthreads();
    int mx = -2147483647;
    for (int t = tid; t < Tseq; t += blockDim.x) mx = max(mx, seg[b*Tseq + t]);
    atomicMax(&smax, mx);
    __syncthreads();
    int mv = smax;
    int mi = 2147483647;
    for (int t = tid; t < Tseq; t += blockDim.x)
        if (seg[b*Tseq + t] == mv) mi = min(mi, t);
    atomicMin(&sidx, mi);
    __syncthreads();
    if (tid == 0) g_first[b] = sidx;
}

// ---------------- rope sin/cos tables --------------------------------------------
__global__ void rope_table_kernel(const int* __restrict__ seg,
                                  const int* __restrict__ cur_ind) {
    int row = blockIdx.x;
    int k   = threadIdx.x;
    int b = row / Tseq, t = row % Tseq;
    int sv = seg[row];
    long long pos = (sv != 0) ? (long long)(t - g_first[b]) : (1ll << 30);
    pos += (long long)cur_ind[0];
    float posf = (float)pos;
    float freq = powf(10000.0f, -((float)(2*k)) / (float)Dh);
    float ang  = posf * freq;
    g_sin[(size_t)row*128 + k] = sinf(ang);
    g_cos[(size_t)row*128 + k] = cosf(ang);
}

// ---------------- pack A (row-major [M][K] float -> frag-major fp16 hi/lo) --------
__global__ void __launch_bounds__(256) pack_a_kernel(
    const float* __restrict__ A, int K,
    uint32_t* __restrict__ Fhi, uint32_t* __restrict__ Flo)
{
    __shared__ float tile[16][68];
    int r0 = blockIdx.x * 16, k0 = blockIdx.y * 64;
    int tid = threadIdx.x;
    {
        int row = tid >> 4, q = tid & 15;
        float4 v = *(const float4*)(A + (size_t)(r0 + row) * K + k0 + q*4);
        *(float4*)&tile[row][q*4] = v;
    }
    __syncthreads();
    int k16l = tid >> 6;
    int r6   = tid & 63;
    int rpair = (r6 >> 5) * 2;
    int lane  = r6 & 31;
    int lr = lane >> 2, lc = lane & 3;
    int cb = k16l*16 + 2*lc + (rpair ? 8 : 0);
    float v00 = tile[lr    ][cb], v01 = tile[lr    ][cb+1];
    float v10 = tile[lr + 8][cb], v11 = tile[lr + 8][cb+1];
    uint32_t h0, l0, h1, l1;
    split2(v00, v01, h0, l0);
    split2(v10, v11, h1, l1);
    int K16 = K >> 4;
    size_t off = ((size_t)blockIdx.x * K16 + blockIdx.y*4 + k16l) * 128 + lane*4 + rpair;
    Fhi[off]   = h0;  Flo[off]   = l0;
    Fhi[off+1] = h1;  Flo[off+1] = l1;
}

// ---------------- pack W ([K][N] float -> B frag-major fp16 hi/lo) ----------------
__global__ void __launch_bounds__(256) pack_w_kernel(
    const float* __restrict__ W, int K, int N,
    uint32_t* __restrict__ Fhi, uint32_t* __restrict__ Flo)
{
    __shared__ float tile[128][9];
    int k0 = blockIdx.x * 128, n0 = blockIdx.y * 8;
    int tid = threadIdx.x;
    {
        int kl = tid >> 1, half = tid & 1;
        float4 v = *(const float4*)(W + (size_t)(k0 + kl) * N + n0 + half*4);
        tile[kl][half*4 + 0] = v.x;
        tile[kl][half*4 + 1] = v.y;
        tile[kl][half*4 + 2] = v.z;
        tile[kl][half*4 + 3] = v.w;
    }
    __syncthreads();
    int k16l = tid >> 5, lane = tid & 31;
    int lr = lane >> 2, lc = lane & 3;
    int kb = k16l * 16;
    float v0 = tile[kb + 2*lc    ][lr];
    float v1 = tile[kb + 2*lc + 1][lr];
    float v2 = tile[kb + 2*lc + 8][lr];
    float v3 = tile[kb + 2*lc + 9][lr];
    uint32_t h0, l0, h1, l1;
    split2(v0, v1, h0, l0);
    split2(v2, v3, h1, l1);
    int K16 = K >> 4;
    size_t off = ((size_t)blockIdx.y * K16 + blockIdx.x*8 + k16l) * 64 + lane*2;
    Fhi[off]   = h0;  Flo[off]   = l0;
    Fhi[off+1] = h1;  Flo[off+1] = l1;
}

// ---------------- frag-major split-fp16 GEMM --------------------------------------
// CTA 128x128, 8 warps (2M x 4N), warp 64x32, K chunk = 64 (4 k16 steps).
// Stage (u32): [Ahi 4096][Alo 4096][Bhi 4096][Blo 4096] = 64KB. 3 stages.
// TERMS=3: ah*bh + al*bh + ah*bl.  TERMS=2: ah*bh + al*bh (Blo plane not loaded).
#define STG_U32 16384
#define NSTG    3
#define GEMM_SMEM (NSTG * STG_U32 * 4)

template<int TERMS>
__global__ void __launch_bounds__(256, 1) gemm_mma_kernel(
    const uint32_t* __restrict__ Ahi, const uint32_t* __restrict__ Alo,
    const uint32_t* __restrict__ Bhi, const uint32_t* __restrict__ Blo,
    float* __restrict__ C, int ldc, int K)
{
    extern __shared__ uint32_t smu[];
    int tid  = threadIdx.x;
    int lane = tid & 31, wid = tid >> 5;
    int wm = wid >> 2, wn = wid & 3;
    int m0 = blockIdx.y * 128, n0 = blockIdx.x * 128;
    int K16 = K >> 4;
    int rb0 = m0 >> 4, nb0 = n0 >> 3;
    const int nc = K >> 6;
    const int NITER = (TERMS == 3) ? 16 : 12;

    float acc[4][4][4];
#pragma unroll
    for (int i = 0; i < 4; i++)
#pragma unroll
        for (int j = 0; j < 4; j++)
#pragma unroll
            for (int r = 0; r < 4; r++) acc[i][j][r] = 0.f;

    uint32_t sbase = smem_u32(smu);

    auto issue = [&](int c, int s) {
        uint32_t sd = sbase + s * (STG_U32 * 4);
        int c4 = c * 4;
#pragma unroll
        for (int i = 0; i < NITER; i++) {
            int idx = tid + i * 256;
            int plane = idx >> 10, sub = idx & 1023;
            const uint32_t* src;
            if (plane < 2) {
                int rb = sub >> 7, k16 = (sub >> 5) & 3, j = sub & 31;
                const uint32_t* pl = plane ? Alo : Ahi;
                src = pl + ((size_t)(rb0 + rb) * K16 + c4 + k16) * 128 + j*4;
            } else {
                int nb = sub >> 6, k16 = (sub >> 4) & 3, j = sub & 15;
                const uint32_t* pl = (plane == 3) ? Blo : Bhi;
                src = pl + ((size_t)(nb0 + nb) * K16 + c4 + k16) * 64 + j*4;
            }
            CP_ASYNC16(sd + idx * 16, src);
        }
    };

    issue(0, 0); CP_COMMIT();
    if (nc > 1) issue(1, 1);
    CP_COMMIT();

    for (int c = 0; c < nc; c++) {
        CP_WAIT1();
        __syncthreads();

        const uint32_t* sA = smu + (c % NSTG) * STG_U32;
        const uint32_t* pA = sA + (wm * 4) * 512 + lane * 4;
        const uint32_t* pB = sA + 8192 + (wn * 4) * 256 + lane * 2;

#pragma unroll
        for (int k16 = 0; k16 < 4; k16++) {
            uint4 AH[4], AL[4];
            uint2 BH[4], BL[4];
#pragma unroll
            for (int mt = 0; mt < 4; mt++) {
                AH[mt] = *(const uint4*)(pA + mt*512 + k16*128);
                AL[mt] = *(const uint4*)(pA + 4096 + mt*512 + k16*128);
            }
#pragma unroll
            for (int nt = 0; nt < 4; nt++) {
                BH[nt] = *(const uint2*)(pB + nt*256 + k16*64);
                if (TERMS == 3)
                    BL[nt] = *(const uint2*)(pB + 4096 + nt*256 + k16*64);
            }
#pragma unroll
            for (int mt = 0; mt < 4; mt++)
#pragma unroll
                for (int nt = 0; nt < 4; nt++) {
                    float* cc = acc[mt][nt];
                    mma_f16(cc, AH[mt].x, AH[mt].y, AH[mt].z, AH[mt].w,
                            BH[nt].x, BH[nt].y);
                    mma_f16(cc, AL[mt].x, AL[mt].y, AL[mt].z, AL[mt].w,
                            BH[nt].x, BH[nt].y);
                    if (TERMS == 3)
                        mma_f16(cc, AH[mt].x, AH[mt].y, AH[mt].z, AH[mt].w,
                                BL[nt].x, BL[nt].y);
                }
        }

        if (c + 2 < nc) issue(c + 2, (c + 2) % NSTG);
        CP_COMMIT();
    }

#pragma unroll
    for (int mt = 0; mt < 4; mt++) {
        int row0 = m0 + wm*64 + mt*16 + (lane >> 2);
#pragma unroll
        for (int nt = 0; nt < 4; nt++) {
            int col = n0 + wn*32 + nt*8 + 2*(lane & 3);
            float* cc = acc[mt][nt];
            *(float2*)(C + (size_t)row0 * ldc + col)       = make_float2(cc[0], cc[1]);
            *(float2*)(C + (size_t)(row0 + 8) * ldc + col) = make_float2(cc[2], cc[3]);
        }
    }
}

// ---------------- RMSNorm + RoPE (q,k) + tf32 rounding (q,k,v) --------------------
__global__ void __launch_bounds__(256) rmsnorm_rope_kernel(
    const float* __restrict__ qsc, const float* __restrict__ ksc)
{
    int bid = blockIdx.x;
    int row = bid >> 4;
    int hi  = bid & 15;
    int tid = threadIdx.x;
    if (hi >= 12) {
        float* p = g_qkv + (size_t)row * QKVN + NH*Dh + NKV*Dh + (hi-12) * Dh;
        p[tid] = cvt_tf32(p[tid]);
        return;
    }
    int off; const float* sc;
    if (hi < NH) { off = hi * Dh;              sc = qsc; }
    else         { off = NH*Dh + (hi-NH) * Dh; sc = ksc; }
    float* p = g_qkv + (size_t)row * QKVN + off;
    float x = p[tid];
    float ss = x * x;
#pragma unroll
    for (int o = 16; o; o >>= 1) ss += __shfl_xor_sync(0xffffffffu, ss, o);
    __shared__ float red[8];
    __shared__ float tot;
    __shared__ float sy[256];
    if ((tid & 31) == 0) red[tid >> 5] = ss;
    __syncthreads();
    if (tid == 0) {
        float t = 0.f;
        for (int i = 0; i < 8; i++) t += red[i];
        tot = t;
    }
    __syncthreads();
    float rms = rsqrtf(tot * (1.0f / Dh) + 1e-6f);
    float y = x * rms * (1.0f + sc[tid]);
    sy[tid] = y;
    __syncthreads();
    int kidx = tid & 127;
    float s_ = g_sin[(size_t)row*128 + kidx];
    float c_ = g_cos[(size_t)row*128 + kidx];
    float out;
    if (tid < 128) out = y * c_ - sy[tid + 128] * s_;
    else           out = y * c_ + sy[tid - 128] * s_;
    p[tid] = cvt_tf32(out);
}

// ---------------- tensor-core flash attention (tf32) ------------------------------
#define ABK       32
#define QS_STR    260
#define KS_STR    260
#define VS_STR    264
#define PS_STR    36
#define QS_OFF    0
#define KS_OFF    16640
#define KS_STG    8320
#define VS_OFF    (KS_OFF + 2*KS_STG)
#define VS_STG    8448
#define PS_OFF    (VS_OFF + 2*VS_STG)
#define RED_OFF   (PS_OFF + 64*PS_STR)
#define SUM_OFF   (RED_OFF + 128)
#define ATTN_SMEM ((SUM_OFF + 128) * 4)
#define SM_SCALE  0.0625f

__global__ void __launch_bounds__(256, 1) attn_mma_kernel(
    uint32_t* __restrict__ AFhi, uint32_t* __restrict__ AFlo)
{
    extern __shared__ float smf[];
    uint32_t sb = smem_u32(smf);
    int tid  = threadIdx.x;
    int lane = tid & 31, wid = tid >> 5;
    int lr = lane >> 2, lc = lane & 3;
    int wm = wid >> 1, wn = wid & 1;

    int q0 = blockIdx.x * 64;
    int h  = blockIdx.y, b = blockIdx.z;
    int kvh = h >> 1;
    const float* baseq = g_qkv + (size_t)b * Tseq * QKVN + h * Dh;
    const float* basek = g_qkv + (size_t)b * Tseq * QKVN + NH*Dh + kvh * Dh;
    const float* basev = g_qkv + (size_t)b * Tseq * QKVN + NH*Dh + NKV*Dh + kvh * Dh;

    auto issueQ = [&]() {
#pragma unroll
        for (int i = 0; i < 16; i++) {
            int idx = tid + i * 256;
            int r = idx >> 6, c = idx & 63;
            CP_ASYNC16(sb + (QS_OFF + r*QS_STR + c*4) * 4,
                       baseq + (size_t)(q0 + r) * QKVN + c*4);
        }
    };
    auto issueKV = [&](int kt, int s) {
#pragma unroll
        for (int i = 0; i < 8; i++) {
            int idx = tid + i * 256;
            int r = idx >> 6, c = idx & 63;
            CP_ASYNC16(sb + (KS_OFF + s*KS_STG + r*KS_STR + c*4) * 4,
                       basek + (size_t)(kt + r) * QKVN + c*4);
        }
#pragma unroll
        for (int i = 0; i < 8; i++) {
            int idx = tid + i * 256;
            int r = idx >> 6, c = idx & 63;
            CP_ASYNC16(sb + (VS_OFF + s*VS_STG + r*VS_STR + c*4) * 4,
                       basev + (size_t)(kt + r) * QKVN + c*4);
        }
    };

    int kstart = q0 - (WINDOW - 1); if (kstart < 0) kstart = 0;
    int kt0 = kstart & ~(ABK - 1);
    int nt  = (q0 + 64 - kt0) >> 5;

    issueQ();
    issueKV(kt0, 0);
    CP_COMMIT();

    int arow = 16*wm + (lane & 7) + ((lane >> 3) & 1) * 8;
    int acol = (lane >> 4) * 4;
    uint32_t qs_addr = sb + (QS_OFF + arow*QS_STR + acol) * 4;
    uint32_t ps_addr = sb + (PS_OFF + arow*PS_STR + acol) * 4;

    int lrow0 = 16*wm + lr;
    int qg0 = q0 + lrow0;

    float m0v = -1e30f, m1v = -1e30f, l0v = 0.f, l1v = 0.f;
    float O[16][4];
#pragma unroll
    for (int i = 0; i < 16; i++)
#pragma unroll
        for (int j = 0; j < 4; j++) O[i][j] = 0.f;

    float* Red = smf + RED_OFF;
    float* Sum = smf + SUM_OFF;

    for (int t = 0; t < nt; t++) {
        int kt = kt0 + t * ABK;
        int s  = t & 1;
        CP_WAIT_ALL();
        __syncthreads();
        if (t + 1 < nt) { issueKV(kt0 + (t+1)*ABK, s ^ 1); CP_COMMIT(); }

        float sacc[2][4];
#pragma unroll
        for (int nb = 0; nb < 2; nb++)
#pragma unroll
            for (int j = 0; j < 4; j++) sacc[nb][j] = 0.f;

        const float* kb0 = smf + KS_OFF + s*KS_STG + (16*wn + lr)*KS_STR + lc;
#pragma unroll 8
        for (int k8 = 0; k8 < 32; k8++) {
            uint32_t a0, a1, a2, a3;
            ldsm_x4(a0, a1, a2, a3, qs_addr + k8*32);
#pragma unroll
            for (int nb = 0; nb < 2; nb++) {
                const float* kb = kb0 + nb*8*KS_STR + k8*8;
                uint32_t b0 = __float_as_uint(kb[0]);
                uint32_t b1 = __float_as_uint(kb[4]);
                mma_tf32(sacc[nb], a0, a1, a2, a3, b0, b1);
            }
        }

        float sv[2][4];
        float mx0 = -1e30f, mx1 = -1e30f;
#pragma unroll
        for (int nb = 0; nb < 2; nb++) {
#pragma unroll
            for (int j = 0; j < 4; j++) {
                int kg = kt + 16*wn + nb*8 + 2*lc + (j & 1);
                int qg = (j < 2) ? qg0 : (qg0 + 8);
                float v = sacc[nb][j] * SM_SCALE;
                bool valid = (kg <= qg) && (qg - kg < WINDOW);
                v = valid ? v : -1e30f;
                sv[nb][j] = v;
                if (j < 2) mx0 = fmaxf(mx0, v); else mx1 = fmaxf(mx1, v);
            }
        }
        mx0 = fmaxf(mx0, __shfl_xor_sync(0xffffffffu, mx0, 1));
        mx0 = fmaxf(mx0, __shfl_xor_sync(0xffffffffu, mx0, 2));
        mx1 = fmaxf(mx1, __shfl_xor_sync(0xffffffffu, mx1, 1));
        mx1 = fmaxf(mx1, __shfl_xor_sync(0xffffffffu, mx1, 2));
        if (lc == 0) {
            Red[wn*64 + lrow0]     = mx0;
            Red[wn*64 + lrow0 + 8] = mx1;
        }
        __syncthreads();
        float mt0 = fmaxf(Red[lrow0],     Red[64 + lrow0]);
        float mt1 = fmaxf(Red[lrow0 + 8], Red[64 + lrow0 + 8]);
        float mn0 = fmaxf(m0v, mt0);
        float mn1 = fmaxf(m1v, mt1);
        float al0 = __expf(m0v - mn0);
        float al1 = __expf(m1v - mn1);

        float s0 = 0.f, s1 = 0.f;
        float pv[2][4];
#pragma unroll
        for (int nb = 0; nb < 2; nb++) {
#pragma unroll
            for (int j = 0; j < 4; j++) {
                float mn = (j < 2) ? mn0 : mn1;
                float p = (sv[nb][j] > -1e29f) ? __expf(sv[nb][j] - mn) : 0.f;
                pv[nb][j] = cvt_tf32(p);
                if (j < 2) s0 += p; else s1 += p;
            }
        }
        s0 += __shfl_xor_sync(0xffffffffu, s0, 1);
        s0 += __shfl_xor_sync(0xffffffffu, s0, 2);
        s1 += __shfl_xor_sync(0xffffffffu, s1, 1);
        s1 += __shfl_xor_sync(0xffffffffu, s1, 2);
        if (lc == 0) {
            Sum[wn*64 + lrow0]     = s0;
            Sum[wn*64 + lrow0 + 8] = s1;
        }
#pragma unroll
        for (int nb = 0; nb < 2; nb++) {
            int col = 16*wn + nb*8 + 2*lc;
            *(float2*)(smf + PS_OFF + lrow0*PS_STR + col)       = make_float2(pv[nb][0], pv[nb][1]);
            *(float2*)(smf + PS_OFF + (lrow0 + 8)*PS_STR + col) = make_float2(pv[nb][2], pv[nb][3]);
        }
        __syncthreads();
        l0v = l0v * al0 + Sum[lrow0]     + Sum[64 + lrow0];
        l1v = l1v * al1 + Sum[lrow0 + 8] + Sum[64 + lrow0 + 8];
        m0v = mn0; m1v = mn1;
#pragma unroll
        for (int i = 0; i < 16; i++) {
            O[i][0] *= al0; O[i][1] *= al0;
            O[i][2] *= al1; O[i][3] *= al1;
        }

        const float* vb0 = smf + VS_OFF + s*VS_STG + lc*VS_STR + 128*wn + lr;
#pragma unroll
        for (int k8 = 0; k8 < 4; k8++) {
            uint32_t p0, p1, p2, p3;
            ldsm_x4(p0, p1, p2, p3, ps_addr + k8*32);
            const float* vb = vb0 + k8*8*VS_STR;
#pragma unroll
            for (int nb = 0; nb < 16; nb++) {
                uint32_t b0 = __float_as_uint(vb[nb*8]);
                uint32_t b1 = __float_as_uint(vb[4*VS_STR + nb*8]);
                mma_tf32(O[nb], p0, p1, p2, p3, b0, b1);
            }
        }
    }

    // ---- epilogue: write frag-major fp16 hi/lo (A of Wo GEMM) ----
    float inv0 = 1.f / l0v, inv1 = 1.f / l1v;
    int rb = ((b * Tseq + q0) >> 4) + wm;
#pragma unroll
    for (int nb = 0; nb < 16; nb++) {
        int k16 = h*16 + 8*wn + (nb >> 1);
        int reg = (nb & 1) * 2;
        size_t off = ((size_t)rb * 128 + k16) * 128 + lane*4 + reg;
        uint32_t h0, l0, h1, l1;
        split2(O[nb][0]*inv0, O[nb][1]*inv0, h0, l0);
        split2(O[nb][2]*inv1, O[nb][3]*inv1, h1, l1);
        AFhi[off]   = h0;  AFlo[off]   = l0;
        AFhi[off+1] = h1;  AFlo[off+1] = l1;
    }
}

// ---------------- launch ------------------------------------------------------------
extern "C" void kernel_launch(void* const* d_in, const int* in_sizes, int n_in,
                              void* d_out, int out_size) {
    const float* x   = (const float*)d_in[0];
    const float* Wq  = (const float*)d_in[1];
    const float* Wk  = (const float*)d_in[2];
    const float* Wv  = (const float*)d_in[3];
    const float* Wo  = (const float*)d_in[4];
    const float* qsc = (const float*)d_in[5];
    const float* ksc = (const float*)d_in[6];
    const int*   seg = (const int*)d_in[7];
    float* out = (float*)d_out;

    const int* cur;
    if (n_in > 9) cur = (const int*)d_in[9];
    else {
        void* zp; cudaGetSymbolAddress(&zp, g_zero_int);
        cur = (const int*)zp;
    }

    float* qkv;
    cudaGetSymbolAddress((void**)&qkv, g_qkv);
    uint32_t *xfh, *xfl, *afh, *afl;
    cudaGetSymbolAddress((void**)&xfh, g_xf_hi); cudaGetSymbolAddress((void**)&xfl, g_xf_lo);
    cudaGetSymbolAddress((void**)&afh, g_af_hi); cudaGetSymbolAddress((void**)&afl, g_af_lo);
    uint32_t *wh, *wl, *woh, *wol;
    cudaGetSymbolAddress((void**)&wh,  g_wqkv_hi); cudaGetSymbolAddress((void**)&wl,  g_wqkv_lo);
    cudaGetSymbolAddress((void**)&woh, g_wo_hi);   cudaGetSymbolAddress((void**)&wol, g_wo_lo);

    cudaFuncSetAttribute(gemm_mma_kernel<2>, cudaFuncAttributeMaxDynamicSharedMemorySize, GEMM_SMEM);
    cudaFuncSetAttribute(gemm_mma_kernel<3>, cudaFuncAttributeMaxDynamicSharedMemorySize, GEMM_SMEM);
    cudaFuncSetAttribute(attn_mma_kernel, cudaFuncAttributeMaxDynamicSharedMemorySize, ATTN_SMEM);

    seg_first_kernel<<<Bsz, 256>>>(seg);
    rope_table_kernel<<<ROWS, 128>>>(seg, cur);

    // pack A (x) and concatenated QKV weights + Wo weights
    const int K16qkv = 2560 / 16;  // 160
    pack_a_kernel<<<dim3(ROWS/16, Hdim/64), 256>>>(x, Hdim, xfh, xfl);
    pack_w_kernel<<<dim3(2560/128, 2048/8), 256>>>(Wq, 2560, 2048, wh, wl);
    pack_w_kernel<<<dim3(2560/128, 1024/8), 256>>>(Wk, 2560, 1024,
        wh + (size_t)256 * K16qkv * 64, wl + (size_t)256 * K16qkv * 64);
    pack_w_kernel<<<dim3(2560/128, 1024/8), 256>>>(Wv, 2560, 1024,
        wh + (size_t)384 * K16qkv * 64, wl + (size_t)384 * K16qkv * 64);
    pack_w_kernel<<<dim3(2048/128, 2560/8), 256>>>(Wo, 2048, 2560, woh, wol);

    // fused QKV projection: one GEMM over N=4096 (q|k|v), 2-term fp16 split
    gemm_mma_kernel<2><<<dim3(QKVN/128, ROWS/128), 256, GEMM_SMEM>>>(
        xfh, xfl, wh, wl, qkv, QKVN, Hdim);

    rmsnorm_rope_kernel<<<ROWS * 16, 256>>>(qsc, ksc);

    attn_mma_kernel<<<dim3(Tseq/64, NH, Bsz), 256, ATTN_SMEM>>>(afh, afl);

    // output projection: 3-term fp16 split
    gemm_mma_kernel<3><<<dim3(Hdim/128, ROWS/128), 256, GEMM_SMEM>>>(
        afh, afl, woh, wol, out, Hdim, ATTN_N);
}

// round 8
// speedup vs baseline: 5.3661x; 1.2334x over previous
#include <cuda_runtime.h>
#include <cuda_bf16.h>
#include <cuda_fp16.h>
#include <math.h>
#include <stdint.h>

#define Bsz    2
#define Tseq   2048
#define Hdim   2560
#define NH     8
#define NKV    4
#define Dh     256
#define WINDOW 1024
#define QKVN   4096          // 2048 q | 1024 k | 1024 v
#define ROWS   (Bsz*Tseq)    // 4096
#define ATTN_N (NH*Dh)       // 2048

// ---------------- scratch (device globals) -----------------------------------
__device__ float  g_qkv[(size_t)ROWS * QKVN];   // fp32 QKV GEMM output
__device__ __half g_qkvh[(size_t)ROWS * QKVN];  // fp16 post-norm/rope q|k|v
__device__ float  g_sin[(size_t)ROWS * (Dh/2)];
__device__ float  g_cos[(size_t)ROWS * (Dh/2)];
__device__ int    g_first[Bsz];
__device__ int    g_zero_int = 0;

// fragment-major fp16 hi/lo planes (uint32 = half2)
__device__ uint32_t g_xf_hi[(size_t)ROWS * Hdim / 2];
__device__ uint32_t g_xf_lo[(size_t)ROWS * Hdim / 2];
__device__ uint32_t g_af_hi[(size_t)ROWS * ATTN_N / 2];   // attn out, frag-major
__device__ uint32_t g_af_lo[(size_t)ROWS * ATTN_N / 2];
__device__ uint32_t g_wqkv_hi[(size_t)4096 * 2560 / 2];   // Wq|Wk|Wv concatenated
__device__ uint32_t g_wqkv_lo[(size_t)4096 * 2560 / 2];
__device__ uint32_t g_wo_hi[(size_t)2560 * 2048 / 2];
__device__ uint32_t g_wo_lo[(size_t)2560 * 2048 / 2];

// ---------------- helpers ------------------------------------------------------
__device__ __forceinline__ uint32_t smem_u32(const void* p) {
    uint32_t a;
    asm("{ .reg .u64 t; cvta.to.shared.u64 t, %1; cvt.u32.u64 %0, t; }"
        : "=r"(a) : "l"(p));
    return a;
}
__device__ __forceinline__ uint32_t h2pack(float x, float y) {
    __half2 h = __floats2half2_rn(x, y);
    return *(uint32_t*)&h;
}
__device__ __forceinline__ void split2(float x, float y, uint32_t& hi, uint32_t& lo) {
    float xh = __half2float(__float2half_rn(x));
    float yh = __half2float(__float2half_rn(y));
    hi = h2pack(xh, yh);
    lo = h2pack(x - xh, y - yh);
}
__device__ __forceinline__ void mma_f16(float* c,
    uint32_t a0, uint32_t a1, uint32_t a2, uint32_t a3,
    uint32_t b0, uint32_t b1)
{
    asm volatile(
        "mma.sync.aligned.m16n8k16.row.col.f32.f16.f16.f32 "
        "{%0,%1,%2,%3}, {%4,%5,%6,%7}, {%8,%9}, {%0,%1,%2,%3};"
        : "+f"(c[0]), "+f"(c[1]), "+f"(c[2]), "+f"(c[3])
        : "r"(a0), "r"(a1), "r"(a2), "r"(a3), "r"(b0), "r"(b1));
}
__device__ __forceinline__ void ldsm_x4(uint32_t& r0, uint32_t& r1,
                                        uint32_t& r2, uint32_t& r3, uint32_t addr)
{
    asm volatile("ldmatrix.sync.aligned.m8n8.x4.shared.b16 {%0,%1,%2,%3}, [%4];"
        : "=r"(r0), "=r"(r1), "=r"(r2), "=r"(r3) : "r"(addr));
}
__device__ __forceinline__ void ldsm_x4t(uint32_t& r0, uint32_t& r1,
                                         uint32_t& r2, uint32_t& r3, uint32_t addr)
{
    asm volatile("ldmatrix.sync.aligned.m8n8.x4.trans.shared.b16 {%0,%1,%2,%3}, [%4];"
        : "=r"(r0), "=r"(r1), "=r"(r2), "=r"(r3) : "r"(addr));
}
#define CP_ASYNC16(dst, src) \
    asm volatile("cp.async.cg.shared.global [%0], [%1], 16;" :: "r"(dst), "l"(src))
#define CP_COMMIT()   asm volatile("cp.async.commit_group;" ::: "memory")
#define CP_WAIT1()    asm volatile("cp.async.wait_group 1;" ::: "memory")
#define CP_WAIT_ALL() asm volatile("cp.async.wait_group 0;" ::: "memory")

// ---------------- pos helper ----------------------------------------------------
__global__ void seg_first_kernel(const int* __restrict__ seg) {
    __shared__ int smax;
    __shared__ int sidx;
    int b = blockIdx.x, tid = threadIdx.x;
    if (tid == 0) { smax = -2147483647; sidx = 2147483647; }
    __syncthreads();
    int mx = -2147483647;
    for (int t = tid; t < Tseq; t += blockDim.x) mx = max(mx, seg[b*Tseq + t]);
    atomicMax(&smax, mx);
    __syncthreads();
    int mv = smax;
    int mi = 2147483647;
    for (int t = tid; t < Tseq; t += blockDim.x)
        if (seg[b*Tseq + t] == mv) mi = min(mi, t);
    atomicMin(&sidx, mi);
    __syncthreads();
    if (tid == 0) g_first[b] = sidx;
}

// ---------------- rope sin/cos tables --------------------------------------------
__global__ void rope_table_kernel(const int* __restrict__ seg,
                                  const int* __restrict__ cur_ind) {
    int row = blockIdx.x;
    int k   = threadIdx.x;
    int b = row / Tseq, t = row % Tseq;
    int sv = seg[row];
    long long pos = (sv != 0) ? (long long)(t - g_first[b]) : (1ll << 30);
    pos += (long long)cur_ind[0];
    float posf = (float)pos;
    float freq = powf(10000.0f, -((float)(2*k)) / (float)Dh);
    float ang  = posf * freq;
    g_sin[(size_t)row*128 + k] = sinf(ang);
    g_cos[(size_t)row*128 + k] = cosf(ang);
}

// ---------------- pack A (row-major [M][K] float -> frag-major fp16 hi/lo) --------
__global__ void __launch_bounds__(256) pack_a_kernel(
    const float* __restrict__ A, int K,
    uint32_t* __restrict__ Fhi, uint32_t* __restrict__ Flo)
{
    __shared__ float tile[16][68];
    int r0 = blockIdx.x * 16, k0 = blockIdx.y * 64;
    int tid = threadIdx.x;
    {
        int row = tid >> 4, q = tid & 15;
        float4 v = *(const float4*)(A + (size_t)(r0 + row) * K + k0 + q*4);
        *(float4*)&tile[row][q*4] = v;
    }
    __syncthreads();
    int k16l = tid >> 6;
    int r6   = tid & 63;
    int rpair = (r6 >> 5) * 2;
    int lane  = r6 & 31;
    int lr = lane >> 2, lc = lane & 3;
    int cb = k16l*16 + 2*lc + (rpair ? 8 : 0);
    float v00 = tile[lr    ][cb], v01 = tile[lr    ][cb+1];
    float v10 = tile[lr + 8][cb], v11 = tile[lr + 8][cb+1];
    uint32_t h0, l0, h1, l1;
    split2(v00, v01, h0, l0);
    split2(v10, v11, h1, l1);
    int K16 = K >> 4;
    size_t off = ((size_t)blockIdx.x * K16 + blockIdx.y*4 + k16l) * 128 + lane*4 + rpair;
    Fhi[off]   = h0;  Flo[off]   = l0;
    Fhi[off+1] = h1;  Flo[off+1] = l1;
}

// ---------------- pack W ([K][N] float -> B frag-major fp16 hi/lo) ----------------
__global__ void __launch_bounds__(256) pack_w_kernel(
    const float* __restrict__ W, int K, int N,
    uint32_t* __restrict__ Fhi, uint32_t* __restrict__ Flo)
{
    __shared__ float tile[128][9];
    int k0 = blockIdx.x * 128, n0 = blockIdx.y * 8;
    int tid = threadIdx.x;
    {
        int kl = tid >> 1, half = tid & 1;
        float4 v = *(const float4*)(W + (size_t)(k0 + kl) * N + n0 + half*4);
        tile[kl][half*4 + 0] = v.x;
        tile[kl][half*4 + 1] = v.y;
        tile[kl][half*4 + 2] = v.z;
        tile[kl][half*4 + 3] = v.w;
    }
    __syncthreads();
    int k16l = tid >> 5, lane = tid & 31;
    int lr = lane >> 2, lc = lane & 3;
    int kb = k16l * 16;
    float v0 = tile[kb + 2*lc    ][lr];
    float v1 = tile[kb + 2*lc + 1][lr];
    float v2 = tile[kb + 2*lc + 8][lr];
    float v3 = tile[kb + 2*lc + 9][lr];
    uint32_t h0, l0, h1, l1;
    split2(v0, v1, h0, l0);
    split2(v2, v3, h1, l1);
    int K16 = K >> 4;
    size_t off = ((size_t)blockIdx.y * K16 + blockIdx.x*8 + k16l) * 64 + lane*2;
    Fhi[off]   = h0;  Flo[off]   = l0;
    Fhi[off+1] = h1;  Flo[off+1] = l1;
}

// ---------------- frag-major split-fp16 GEMM --------------------------------------
#define STG_U32 16384
#define NSTG    3
#define GEMM_SMEM (NSTG * STG_U32 * 4)

template<int TERMS>
__global__ void __launch_bounds__(256, 1) gemm_mma_kernel(
    const uint32_t* __restrict__ Ahi, const uint32_t* __restrict__ Alo,
    const uint32_t* __restrict__ Bhi, const uint32_t* __restrict__ Blo,
    float* __restrict__ C, int ldc, int K)
{
    extern __shared__ uint32_t smu[];
    int tid  = threadIdx.x;
    int lane = tid & 31, wid = tid >> 5;
    int wm = wid >> 2, wn = wid & 3;
    int m0 = blockIdx.y * 128, n0 = blockIdx.x * 128;
    int K16 = K >> 4;
    int rb0 = m0 >> 4, nb0 = n0 >> 3;
    const int nc = K >> 6;
    const int NITER = (TERMS == 3) ? 16 : 12;

    float acc[4][4][4];
#pragma unroll
    for (int i = 0; i < 4; i++)
#pragma unroll
        for (int j = 0; j < 4; j++)
#pragma unroll
            for (int r = 0; r < 4; r++) acc[i][j][r] = 0.f;

    uint32_t sbase = smem_u32(smu);

    auto issue = [&](int c, int s) {
        uint32_t sd = sbase + s * (STG_U32 * 4);
        int c4 = c * 4;
#pragma unroll
        for (int i = 0; i < NITER; i++) {
            int idx = tid + i * 256;
            int plane = idx >> 10, sub = idx & 1023;
            const uint32_t* src;
            if (plane < 2) {
                int rb = sub >> 7, k16 = (sub >> 5) & 3, j = sub & 31;
                const uint32_t* pl = plane ? Alo : Ahi;
                src = pl + ((size_t)(rb0 + rb) * K16 + c4 + k16) * 128 + j*4;
            } else {
                int nb = sub >> 6, k16 = (sub >> 4) & 3, j = sub & 15;
                const uint32_t* pl = (plane == 3) ? Blo : Bhi;
                src = pl + ((size_t)(nb0 + nb) * K16 + c4 + k16) * 64 + j*4;
            }
            CP_ASYNC16(sd + idx * 16, src);
        }
    };

    issue(0, 0); CP_COMMIT();
    if (nc > 1) issue(1, 1);
    CP_COMMIT();

    for (int c = 0; c < nc; c++) {
        CP_WAIT1();
        __syncthreads();

        const uint32_t* sA = smu + (c % NSTG) * STG_U32;
        const uint32_t* pA = sA + (wm * 4) * 512 + lane * 4;
        const uint32_t* pB = sA + 8192 + (wn * 4) * 256 + lane * 2;

#pragma unroll
        for (int k16 = 0; k16 < 4; k16++) {
            uint4 AH[4], AL[4];
            uint2 BH[4], BL[4];
#pragma unroll
            for (int mt = 0; mt < 4; mt++) {
                AH[mt] = *(const uint4*)(pA + mt*512 + k16*128);
                AL[mt] = *(const uint4*)(pA + 4096 + mt*512 + k16*128);
            }
#pragma unroll
            for (int nt = 0; nt < 4; nt++) {
                BH[nt] = *(const uint2*)(pB + nt*256 + k16*64);
                if (TERMS == 3)
                    BL[nt] = *(const uint2*)(pB + 4096 + nt*256 + k16*64);
            }
#pragma unroll
            for (int mt = 0; mt < 4; mt++)
#pragma unroll
                for (int nt = 0; nt < 4; nt++) {
                    float* cc = acc[mt][nt];
                    mma_f16(cc, AH[mt].x, AH[mt].y, AH[mt].z, AH[mt].w,
                            BH[nt].x, BH[nt].y);
                    mma_f16(cc, AL[mt].x, AL[mt].y, AL[mt].z, AL[mt].w,
                            BH[nt].x, BH[nt].y);
                    if (TERMS == 3)
                        mma_f16(cc, AH[mt].x, AH[mt].y, AH[mt].z, AH[mt].w,
                                BL[nt].x, BL[nt].y);
                }
        }

        if (c + 2 < nc) issue(c + 2, (c + 2) % NSTG);
        CP_COMMIT();
    }

#pragma unroll
    for (int mt = 0; mt < 4; mt++) {
        int row0 = m0 + wm*64 + mt*16 + (lane >> 2);
#pragma unroll
        for (int nt = 0; nt < 4; nt++) {
            int col = n0 + wn*32 + nt*8 + 2*(lane & 3);
            float* cc = acc[mt][nt];
            *(float2*)(C + (size_t)row0 * ldc + col)       = make_float2(cc[0], cc[1]);
            *(float2*)(C + (size_t)(row0 + 8) * ldc + col) = make_float2(cc[2], cc[3]);
        }
    }
}

// ---------------- RMSNorm + RoPE (q,k) + fp16 convert (q,k,v) ---------------------
// grid = ROWS*16: hi<8 q head, 8..11 k head, 12..15 v head (convert only)
__global__ void __launch_bounds__(256) rmsnorm_rope_kernel(
    const float* __restrict__ qsc, const float* __restrict__ ksc)
{
    int bid = blockIdx.x;
    int row = bid >> 4;
    int hi  = bid & 15;
    int tid = threadIdx.x;
    if (hi >= 12) {
        size_t o = (size_t)row * QKVN + NH*Dh + NKV*Dh + (hi-12) * Dh + tid;
        g_qkvh[o] = __float2half_rn(g_qkv[o]);
        return;
    }
    int off; const float* sc;
    if (hi < NH) { off = hi * Dh;              sc = qsc; }
    else         { off = NH*Dh + (hi-NH) * Dh; sc = ksc; }
    const float* p = g_qkv + (size_t)row * QKVN + off;
    float x = p[tid];
    float ss = x * x;
#pragma unroll
    for (int o = 16; o; o >>= 1) ss += __shfl_xor_sync(0xffffffffu, ss, o);
    __shared__ float red[8];
    __shared__ float tot;
    __shared__ float sy[256];
    if ((tid & 31) == 0) red[tid >> 5] = ss;
    __syncthreads();
    if (tid == 0) {
        float t = 0.f;
        for (int i = 0; i < 8; i++) t += red[i];
        tot = t;
    }
    __syncthreads();
    float rms = rsqrtf(tot * (1.0f / Dh) + 1e-6f);
    float y = x * rms * (1.0f + sc[tid]);
    sy[tid] = y;
    __syncthreads();
    int kidx = tid & 127;
    float s_ = g_sin[(size_t)row*128 + kidx];
    float c_ = g_cos[(size_t)row*128 + kidx];
    float out;
    if (tid < 128) out = y * c_ - sy[tid + 128] * s_;
    else           out = y * c_ + sy[tid - 128] * s_;
    g_qkvh[(size_t)row * QKVN + off + tid] = __float2half_rn(out);
}

// ---------------- fp16 tensor-core flash attention --------------------------------
// BQ=64, BKT=32, 8 warps (4 q-rowgroups x 2 halves). All tiles fp16 in smem.
#define ABK       32
#define QS_H      264
#define KS_H      264
#define VS_H      264
#define PS_H      40
#define QS_B      0
#define KS_B      (64*QS_H*2)           // 33792
#define KS_STG_B  (32*KS_H*2)           // 16896
#define VS_B      (KS_B + 2*KS_STG_B)   // 67584
#define VS_STG_B  16896
#define PS_B      (VS_B + 2*VS_STG_B)   // 101376
#define RED_B     (PS_B + 64*PS_H*2)    // 106496
#define SUM_B     (RED_B + 512)
#define ATTN_SMEM (SUM_B + 512)         // 107520
#define SM_SCALE  0.0625f

__global__ void __launch_bounds__(256, 2) attn_mma_kernel(
    uint32_t* __restrict__ AFhi, uint32_t* __restrict__ AFlo)
{
    extern __shared__ char smc[];
    __half* smh = (__half*)smc;
    uint32_t sb = smem_u32(smc);
    int tid  = threadIdx.x;
    int lane = tid & 31, wid = tid >> 5;
    int lr = lane >> 2, lc = lane & 3;
    int wm = wid >> 1, wn = wid & 1;

    int q0 = blockIdx.x * 64;
    int h  = blockIdx.y, b = blockIdx.z;
    int kvh = h >> 1;
    const __half* baseq = g_qkvh + (size_t)b * Tseq * QKVN + h * Dh;
    const __half* basek = g_qkvh + (size_t)b * Tseq * QKVN + NH*Dh + kvh * Dh;
    const __half* basev = g_qkvh + (size_t)b * Tseq * QKVN + NH*Dh + NKV*Dh + kvh * Dh;

    auto issueQ = [&]() {
#pragma unroll
        for (int i = 0; i < 8; i++) {
            int idx = tid + i * 256;
            int r = idx >> 5, c8 = idx & 31;
            CP_ASYNC16(sb + QS_B + (r*QS_H + c8*8)*2,
                       baseq + (size_t)(q0 + r) * QKVN + c8*8);
        }
    };
    auto issueKV = [&](int kt, int s) {
#pragma unroll
        for (int i = 0; i < 4; i++) {
            int idx = tid + i * 256;
            int r = idx >> 5, c8 = idx & 31;
            CP_ASYNC16(sb + KS_B + s*KS_STG_B + (r*KS_H + c8*8)*2,
                       basek + (size_t)(kt + r) * QKVN + c8*8);
        }
#pragma unroll
        for (int i = 0; i < 4; i++) {
            int idx = tid + i * 256;
            int r = idx >> 5, c8 = idx & 31;
            CP_ASYNC16(sb + VS_B + s*VS_STG_B + (r*VS_H + c8*8)*2,
                       basev + (size_t)(kt + r) * QKVN + c8*8);
        }
    };

    int kstart = q0 - (WINDOW - 1); if (kstart < 0) kstart = 0;
    int kt0 = kstart & ~(ABK - 1);
    int nt  = (q0 + 64 - kt0) >> 5;

    issueQ();
    issueKV(kt0, 0);
    CP_COMMIT();

    // ldmatrix A addresses (Q and P): row = 16wm + lane%16, colblock = (lane/16)*8 halves
    int arow = 16*wm + (lane & 15);
    int acol8 = (lane >> 4) * 8;
    uint32_t qs_addr = sb + QS_B + (arow*QS_H + acol8)*2;
    uint32_t ps_addr = sb + PS_B + (arow*PS_H + acol8)*2;
    // ldmatrix.trans V lane address components
    int vkey = (lane & 7) + 8*((lane >> 3) & 1);
    int vd8  = 8*(lane >> 4);

    int lrow0 = 16*wm + lr;
    int qg0 = q0 + lrow0;

    float m0v = -1e30f, m1v = -1e30f, l0v = 0.f, l1v = 0.f;
    float O[16][4];
#pragma unroll
    for (int i = 0; i < 16; i++)
#pragma unroll
        for (int j = 0; j < 4; j++) O[i][j] = 0.f;

    float* Red = (float*)(smc + RED_B);
    float* Sum = (float*)(smc + SUM_B);

    for (int t = 0; t < nt; t++) {
        int kt = kt0 + t * ABK;
        int s  = t & 1;
        CP_WAIT_ALL();
        __syncthreads();
        if (t + 1 < nt) { issueKV(kt0 + (t+1)*ABK, s ^ 1); CP_COMMIT(); }

        // ---- S = Q K^T (fp16 k16) ----
        float sacc[2][4];
#pragma unroll
        for (int nb = 0; nb < 2; nb++)
#pragma unroll
            for (int j = 0; j < 4; j++) sacc[nb][j] = 0.f;

        const __half* kb0 = smh + KS_B/2 + s*(KS_STG_B/2) + (16*wn + lr)*KS_H + 2*lc;
#pragma unroll
        for (int k16 = 0; k16 < 16; k16++) {
            uint32_t a0, a1, a2, a3;
            ldsm_x4(a0, a1, a2, a3, qs_addr + k16*32);
#pragma unroll
            for (int nb = 0; nb < 2; nb++) {
                const __half* kb = kb0 + nb*8*KS_H + k16*16;
                uint32_t b0 = *(const uint32_t*)kb;
                uint32_t b1 = *(const uint32_t*)(kb + 8);
                mma_f16(sacc[nb], a0, a1, a2, a3, b0, b1);
            }
        }

        // ---- masked scale + online softmax ----
        float sv[2][4];
        float mx0 = -1e30f, mx1 = -1e30f;
#pragma unroll
        for (int nb = 0; nb < 2; nb++) {
#pragma unroll
            for (int j = 0; j < 4; j++) {
                int kg = kt + 16*wn + nb*8 + 2*lc + (j & 1);
                int qg = (j < 2) ? qg0 : (qg0 + 8);
                float v = sacc[nb][j] * SM_SCALE;
                bool valid = (kg <= qg) && (qg - kg < WINDOW);
                v = valid ? v : -1e30f;
                sv[nb][j] = v;
                if (j < 2) mx0 = fmaxf(mx0, v); else mx1 = fmaxf(mx1, v);
            }
        }
        mx0 = fmaxf(mx0, __shfl_xor_sync(0xffffffffu, mx0, 1));
        mx0 = fmaxf(mx0, __shfl_xor_sync(0xffffffffu, mx0, 2));
        mx1 = fmaxf(mx1, __shfl_xor_sync(0xffffffffu, mx1, 1));
        mx1 = fmaxf(mx1, __shfl_xor_sync(0xffffffffu, mx1, 2));
        if (lc == 0) {
            Red[wn*64 + lrow0]     = mx0;
            Red[wn*64 + lrow0 + 8] = mx1;
        }
        __syncthreads();
        float mt0 = fmaxf(Red[lrow0],     Red[64 + lrow0]);
        float mt1 = fmaxf(Red[lrow0 + 8], Red[64 + lrow0 + 8]);
        float mn0 = fmaxf(m0v, mt0);
        float mn1 = fmaxf(m1v, mt1);
        float al0 = __expf(m0v - mn0);
        float al1 = __expf(m1v - mn1);

        float s0 = 0.f, s1 = 0.f;
        float pv[2][4];
#pragma unroll
        for (int nb = 0; nb < 2; nb++) {
#pragma unroll
            for (int j = 0; j < 4; j++) {
                float mn = (j < 2) ? mn0 : mn1;
                float p = (sv[nb][j] > -1e29f) ? __expf(sv[nb][j] - mn) : 0.f;
                pv[nb][j] = p;
                if (j < 2) s0 += p; else s1 += p;
            }
        }
        s0 += __shfl_xor_sync(0xffffffffu, s0, 1);
        s0 += __shfl_xor_sync(0xffffffffu, s0, 2);
        s1 += __shfl_xor_sync(0xffffffffu, s1, 1);
        s1 += __shfl_xor_sync(0xffffffffu, s1, 2);
        if (lc == 0) {
            Sum[wn*64 + lrow0]     = s0;
            Sum[wn*64 + lrow0 + 8] = s1;
        }
        // write P tiles as fp16
#pragma unroll
        for (int nb = 0; nb < 2; nb++) {
            int col = 16*wn + nb*8 + 2*lc;
            *(uint32_t*)(smh + PS_B/2 + lrow0*PS_H + col)       = h2pack(pv[nb][0], pv[nb][1]);
            *(uint32_t*)(smh + PS_B/2 + (lrow0 + 8)*PS_H + col) = h2pack(pv[nb][2], pv[nb][3]);
        }
        __syncthreads();
        l0v = l0v * al0 + Sum[lrow0]     + Sum[64 + lrow0];
        l1v = l1v * al1 + Sum[lrow0 + 8] + Sum[64 + lrow0 + 8];
        m0v = mn0; m1v = mn1;
#pragma unroll
        for (int i = 0; i < 16; i++) {
            O[i][0] *= al0; O[i][1] *= al0;
            O[i][2] *= al1; O[i][3] *= al1;
        }

        // ---- O += P V (fp16 k16, V via ldmatrix.trans) ----
        uint32_t vs_base = sb + VS_B + s*VS_STG_B + (vkey*VS_H + 128*wn + vd8)*2;
#pragma unroll
        for (int k16 = 0; k16 < 2; k16++) {
            uint32_t p0, p1, p2, p3;
            ldsm_x4(p0, p1, p2, p3, ps_addr + k16*32);
            uint32_t va = vs_base + k16*16*VS_H*2;
#pragma unroll
            for (int nb2 = 0; nb2 < 8; nb2++) {
                uint32_t r0, r1, r2, r3;
                ldsm_x4t(r0, r1, r2, r3, va + nb2*32);
                mma_f16(O[nb2*2],     p0, p1, p2, p3, r0, r1);
                mma_f16(O[nb2*2 + 1], p0, p1, p2, p3, r2, r3);
            }
        }
    }

    // ---- epilogue: frag-major fp16 hi/lo (A of Wo GEMM) ----
    float inv0 = 1.f / l0v, inv1 = 1.f / l1v;
    int rb = ((b * Tseq + q0) >> 4) + wm;
#pragma unroll
    for (int nb = 0; nb < 16; nb++) {
        int k16 = h*16 + 8*wn + (nb >> 1);
        int reg = (nb & 1) * 2;
        size_t off = ((size_t)rb * 128 + k16) * 128 + lane*4 + reg;
        uint32_t h0, l0, h1, l1;
        split2(O[nb][0]*inv0, O[nb][1]*inv0, h0, l0);
        split2(O[nb][2]*inv1, O[nb][3]*inv1, h1, l1);
        AFhi[off]   = h0;  AFlo[off]   = l0;
        AFhi[off+1] = h1;  AFlo[off+1] = l1;
    }
}

// ---------------- launch ------------------------------------------------------------
extern "C" void kernel_launch(void* const* d_in, const int* in_sizes, int n_in,
                              void* d_out, int out_size) {
    const float* x   = (const float*)d_in[0];
    const float* Wq  = (const float*)d_in[1];
    const float* Wk  = (const float*)d_in[2];
    const float* Wv  = (const float*)d_in[3];
    const float* Wo  = (const float*)d_in[4];
    const float* qsc = (const float*)d_in[5];
    const float* ksc = (const float*)d_in[6];
    const int*   seg = (const int*)d_in[7];
    float* out = (float*)d_out;

    const int* cur;
    if (n_in > 9) cur = (const int*)d_in[9];
    else {
        void* zp; cudaGetSymbolAddress(&zp, g_zero_int);
        cur = (const int*)zp;
    }

    float* qkv;
    cudaGetSymbolAddress((void**)&qkv, g_qkv);
    uint32_t *xfh, *xfl, *afh, *afl;
    cudaGetSymbolAddress((void**)&xfh, g_xf_hi); cudaGetSymbolAddress((void**)&xfl, g_xf_lo);
    cudaGetSymbolAddress((void**)&afh, g_af_hi); cudaGetSymbolAddress((void**)&afl, g_af_lo);
    uint32_t *wh, *wl, *woh, *wol;
    cudaGetSymbolAddress((void**)&wh,  g_wqkv_hi); cudaGetSymbolAddress((void**)&wl,  g_wqkv_lo);
    cudaGetSymbolAddress((void**)&woh, g_wo_hi);   cudaGetSymbolAddress((void**)&wol, g_wo_lo);

    cudaFuncSetAttribute(gemm_mma_kernel<2>, cudaFuncAttributeMaxDynamicSharedMemorySize, GEMM_SMEM);
    cudaFuncSetAttribute(attn_mma_kernel, cudaFuncAttributeMaxDynamicSharedMemorySize, ATTN_SMEM);

    seg_first_kernel<<<Bsz, 256>>>(seg);
    rope_table_kernel<<<ROWS, 128>>>(seg, cur);

    const int K16qkv = 2560 / 16;  // 160
    pack_a_kernel<<<dim3(ROWS/16, Hdim/64), 256>>>(x, Hdim, xfh, xfl);
    pack_w_kernel<<<dim3(2560/128, 2048/8), 256>>>(Wq, 2560, 2048, wh, wl);
    pack_w_kernel<<<dim3(2560/128, 1024/8), 256>>>(Wk, 2560, 1024,
        wh + (size_t)256 * K16qkv * 64, wl + (size_t)256 * K16qkv * 64);
    pack_w_kernel<<<dim3(2560/128, 1024/8), 256>>>(Wv, 2560, 1024,
        wh + (size_t)384 * K16qkv * 64, wl + (size_t)384 * K16qkv * 64);
    pack_w_kernel<<<dim3(2048/128, 2560/8), 256>>>(Wo, 2048, 2560, woh, wol);

    // fused QKV projection (2-term fp16 split)
    gemm_mma_kernel<2><<<dim3(QKVN/128, ROWS/128), 256, GEMM_SMEM>>>(
        xfh, xfl, wh, wl, qkv, QKVN, Hdim);

    rmsnorm_rope_kernel<<<ROWS * 16, 256>>>(qsc, ksc);

    attn_mma_kernel<<<dim3(Tseq/64, NH, Bsz), 256, ATTN_SMEM>>>(afh, afl);

    // output projection (2-term fp16 split: full-precision A @ fp16(Wo))
    gemm_mma_kernel<2><<<dim3(Hdim/128, ROWS/128), 256, GEMM_SMEM>>>(
        afh, afl, woh, wol, out, Hdim, ATTN_N);
}